// round 13
// baseline (speedup 1.0000x reference)
#include <cuda_runtime.h>
#include <cuda_fp16.h>
#include <stdlib.h>
#include <math.h>
#include <stdint.h>

__attribute__((constructor)) static void _force_eager_module_load() {
    setenv("CUDA_MODULE_LOADING", "EAGER", 1);
}

#define N_NODES 50000
#define N_EDGES 400000
#define MAXD 1024
#define BN_EPS 1e-5f
#define NYB 391   // ceil(50000/128)

// ---- consolidated scratch (float units; halves view via GH) ------------------
#define HX_H    0            // N*1024 halves (big ping)
#define HY_H    51200000     // N*512 halves (pong)
#define HAGG_H  76800000     // N*512 halves (agg)
#define HXIN_H  102400000    // N*128 halves (x fp16)
#define HWT_H   108800000    // transposed fp16 weights
#define ZW_F    55500000     // N*80 fp32 (layer-5 z|w)
#define A40_F   59500000     // N*40 fp32
#define IDG_F   61500000
#define ST_F    61550080     // a at +0, c at +MAXD
#define PART_F  61552128     // NYB x 2048
#define BF_F    62352896
#define CWL_F   62354944
#define SCR_TOTAL 62356224
__device__ __align__(256) float g_scr[SCR_TOTAL];
#define GH ((__half*)g_scr)

// ================= CSR build (atomics only in d_out) =========================
__global__ void zero_ints(int* __restrict__ p, int n) {
    int i = blockIdx.x * blockDim.x + threadIdx.x;
    if (i < n) p[i] = 0;
}

__global__ void hist_kernel(const int* __restrict__ dst, int* __restrict__ deg, int E) {
    int i = blockIdx.x * blockDim.x + threadIdx.x;
    if (i < E) atomicAdd(&deg[dst[i]], 1);
}

__global__ void scan1(const int* __restrict__ deg, int* __restrict__ off, int* __restrict__ bsum) {
    __shared__ int sh[1024];
    int tid = threadIdx.x;
    int base = blockIdx.x * 4096 + tid * 4;
    int v0 = 0, v1 = 0, v2 = 0, v3 = 0;
    if (base + 3 < N_NODES) {
        int4 v = *(const int4*)(deg + base);
        v0 = v.x; v1 = v.y; v2 = v.z; v3 = v.w;
    } else {
        if (base + 0 < N_NODES) v0 = deg[base + 0];
        if (base + 1 < N_NODES) v1 = deg[base + 1];
        if (base + 2 < N_NODES) v2 = deg[base + 2];
        if (base + 3 < N_NODES) v3 = deg[base + 3];
    }
    int s = v0 + v1 + v2 + v3;
    sh[tid] = s;
    __syncthreads();
    for (int o = 1; o < 1024; o <<= 1) {
        int t = (tid >= o) ? sh[tid - o] : 0;
        __syncthreads();
        sh[tid] += t;
        __syncthreads();
    }
    int ex = sh[tid] - s;
    if (base + 0 < N_NODES) off[base + 0] = ex;
    if (base + 1 < N_NODES) off[base + 1] = ex + v0;
    if (base + 2 < N_NODES) off[base + 2] = ex + v0 + v1;
    if (base + 3 < N_NODES) off[base + 3] = ex + v0 + v1 + v2;
    if (tid == 1023) bsum[blockIdx.x] = sh[1023];
}

__global__ void scan2(int* __restrict__ bsum) {
    if (threadIdx.x == 0) {
        int run = 0;
        for (int i = 0; i < 13; i++) { int v = bsum[i]; bsum[i] = run; run += v; }
        bsum[13] = run;
    }
}

__global__ void scan3(int* __restrict__ off, const int* __restrict__ bsum) {
    int tid = threadIdx.x;
    int add = bsum[blockIdx.x];
    int base = blockIdx.x * 4096 + tid * 4;
#pragma unroll
    for (int j = 0; j < 4; j++)
        if (base + j < N_NODES) off[base + j] += add;
    if (blockIdx.x == 0 && tid == 0) off[N_NODES] = bsum[13];
}

__global__ void invdeg_kernel(const int* __restrict__ deg) {
    int i = blockIdx.x * blockDim.x + threadIdx.x;
    if (i < N_NODES) g_scr[IDG_F + i] = (deg[i] > 0) ? (1.0f / (float)deg[i]) : 0.0f;
}

__global__ void csr_scatter(const int* __restrict__ src, const int* __restrict__ dst,
                            const int* __restrict__ off, int* __restrict__ cur,
                            int* __restrict__ col, int E) {
    int e = blockIdx.x * blockDim.x + threadIdx.x;
    if (e >= E) return;
    int d = dst[e];
    int p = atomicAdd(&cur[d], 1);
    col[off[d] + p] = src[e];
}

// ================= x -> fp16 ==================================================
__global__ void xconv(const float* __restrict__ x) {
    int i = blockIdx.x * blockDim.x + threadIdx.x;
    if (i < N_NODES * 32) {
        float4 v = ((const float4*)x)[i];
        __half2* o = (__half2*)(GH + HXIN_H);
        o[2 * i] = __floats2half2_rn(v.x, v.y);
        o[2 * i + 1] = __floats2half2_rn(v.z, v.w);
    }
}

// ================= gather-mean fp16 (warp per node) ==========================
template <int NU>
__global__ void gather16(int inOffH, int outOffH,
                         const int* __restrict__ off, const int* __restrict__ col,
                         int d4) {
    const uint2* base = (const uint2*)(GH + inOffH);
    uint2* out = (uint2*)(GH + outOffH);
    int node = (blockIdx.x * blockDim.x + threadIdx.x) >> 5;
    int lane = threadIdx.x & 31;
    if (node >= N_NODES) return;
    int s = off[node], e = off[node + 1];
    float sdeg = g_scr[IDG_F + node];
    float2 acc[NU][2];
#pragma unroll
    for (int i = 0; i < NU; i++) {
        acc[i][0] = make_float2(0.f, 0.f);
        acc[i][1] = make_float2(0.f, 0.f);
    }
    for (int j = s; j < e; j++) {
        const uint2* row = base + (size_t)col[j] * d4;
#pragma unroll
        for (int i = 0; i < NU; i++) {
            uint2 v = row[lane + 32 * i];
            uint32_t ux = v.x, uy = v.y;
            float2 f0 = __half22float2(*reinterpret_cast<__half2*>(&ux));
            float2 f1 = __half22float2(*reinterpret_cast<__half2*>(&uy));
            acc[i][0].x += f0.x; acc[i][0].y += f0.y;
            acc[i][1].x += f1.x; acc[i][1].y += f1.y;
        }
    }
    uint2* orow = out + (size_t)node * d4;
#pragma unroll
    for (int i = 0; i < NU; i++) {
        __half2 h0 = __floats2half2_rn(acc[i][0].x * sdeg, acc[i][0].y * sdeg);
        __half2 h1 = __floats2half2_rn(acc[i][1].x * sdeg, acc[i][1].y * sdeg);
        uint2 v;
        v.x = *reinterpret_cast<uint32_t*>(&h0);
        v.y = *reinterpret_cast<uint32_t*>(&h1);
        orow[lane + 32 * i] = v;
    }
}

// ================= gather-mean fp32 for layer-5 z (40 cols) ==================
__global__ void gather40(const int* __restrict__ off, const int* __restrict__ col) {
    const float4* base = (const float4*)(g_scr + ZW_F);
    float4* out = (float4*)(g_scr + A40_F);
    int node = (blockIdx.x * blockDim.x + threadIdx.x) >> 5;
    int lane = threadIdx.x & 31;
    if (node >= N_NODES) return;
    int s = off[node], e = off[node + 1];
    float sdeg = g_scr[IDG_F + node];
    float4 acc = make_float4(0.f, 0.f, 0.f, 0.f);
    if (lane < 10) {
        for (int j = s; j < e; j++) {
            float4 v = base[(size_t)col[j] * 20 + lane];
            acc.x += v.x; acc.y += v.y; acc.z += v.z; acc.w += v.w;
        }
        acc.x *= sdeg; acc.y *= sdeg; acc.z *= sdeg; acc.w *= sdeg;
        out[(size_t)node * 10 + lane] = acc;
    }
}

// ================= helpers ===================================================
__device__ __forceinline__ void mma_f16(float c[4], uint32_t a0, uint32_t a1,
                                        uint32_t a2, uint32_t a3,
                                        uint32_t b0, uint32_t b1) {
    asm volatile(
        "mma.sync.aligned.m16n8k16.row.col.f32.f16.f16.f32 "
        "{%0,%1,%2,%3}, {%4,%5,%6,%7}, {%8,%9}, {%0,%1,%2,%3};"
        : "+f"(c[0]), "+f"(c[1]), "+f"(c[2]), "+f"(c[3])
        : "r"(a0), "r"(a1), "r"(a2), "r"(a3), "r"(b0), "r"(b1));
}

__device__ __forceinline__ void cp16(uint32_t dst, const void* src) {
    asm volatile("cp.async.cg.shared.global [%0], [%1], 16;\n"
                 :: "r"(dst), "l"(src) : "memory");
}

// ================= fp16 dual GEMM, BN=128 (layers 1, 2, 5) ===================
template <int OUTF32>
__global__ __launch_bounds__(256, 2) void gemm_f16(
    int aOff1, int aOff2, int wtOff,
    int M, int K1, int K2, int Nd,
    int useCwl, int outOff, int doRelu, int doBN)
{
    extern __shared__ float smem[];
    uint32_t sbase = (uint32_t)__cvta_generic_to_shared(smem);
    int tid = threadIdx.x, lane = tid & 31, wid = tid >> 5;
    int bm = blockIdx.y * 128, bn = blockIdx.x * 128;
    int wm = (wid >> 2) * 64, wn = (wid & 3) * 32;
    int lr = lane >> 2, lc = lane & 3;
    int KT = K1 + K2;
    int NCH = KT / 32;

    float acc[4][4][4];
#pragma unroll
    for (int i = 0; i < 4; i++)
#pragma unroll
        for (int j = 0; j < 4; j++)
#pragma unroll
            for (int k = 0; k < 4; k++) acc[i][j][k] = 0.0f;

    auto issue = [&](int st, int c) {
        uint32_t aReg = sbase + st * 16384;
        uint32_t bReg = aReg + 8192;
        int ck = c * 32;
        const __half* Asrc;
        int astride, acol;
        if (ck < K1) { Asrc = GH + aOff1; astride = K1; acol = ck; }
        else         { Asrc = GH + aOff2; astride = K2; acol = ck - K1; }
#pragma unroll
        for (int i = 0; i < 2; i++) {
            int idx = tid + i * 256;
            int r = idx >> 2, c16 = idx & 3;
            int ar = bm + r; if (ar >= M) ar = M - 1;
            const void* src = Asrc + (size_t)ar * astride + acol + c16 * 8;
            int w = (c16 * 4) ^ (((r >> 1) & 3) << 2);
            cp16(aReg + (uint32_t)(r * 64 + w * 4), src);
        }
#pragma unroll
        for (int i = 0; i < 2; i++) {
            int idx = tid + i * 256;
            int n = idx >> 2, c16 = idx & 3;
            const void* src = GH + wtOff + (size_t)(bn + n) * KT + ck + c16 * 8;
            int w = (c16 * 4) ^ (((n >> 1) & 3) << 2);
            cp16(bReg + (uint32_t)(n * 64 + w * 4), src);
        }
        asm volatile("cp.async.commit_group;\n" ::: "memory");
    };

    issue(0, 0);
    if (NCH > 1) issue(1, 1);
    else asm volatile("cp.async.commit_group;\n" ::: "memory");

    int swz = ((lr >> 1) & 3) << 2;

    int s = 0;
    for (int c = 0; c < NCH; c++) {
        asm volatile("cp.async.wait_group 1;\n" ::: "memory");
        __syncthreads();
        int s2 = s + 2; if (s2 >= 3) s2 -= 3;
        if (c + 2 < NCH) issue(s2, c + 2);
        else asm volatile("cp.async.commit_group;\n" ::: "memory");

        const uint32_t* As = (const uint32_t*)smem + s * 4096;
        const uint32_t* Bs = As + 2048;
#pragma unroll
        for (int ks = 0; ks < 2; ks++) {
            int kb = ks * 8;
            int x0 = (kb + lc) ^ swz, x1 = (kb + lc + 4) ^ swz;
            uint32_t af[4][4], bf[4][2];
#pragma unroll
            for (int mt = 0; mt < 4; mt++) {
                int r = wm + mt * 16 + lr;
                af[mt][0] = As[r * 16 + x0];
                af[mt][1] = As[(r + 8) * 16 + x0];
                af[mt][2] = As[r * 16 + x1];
                af[mt][3] = As[(r + 8) * 16 + x1];
            }
#pragma unroll
            for (int nt = 0; nt < 4; nt++) {
                int n = wn + nt * 8 + lr;
                bf[nt][0] = Bs[n * 16 + x0];
                bf[nt][1] = Bs[n * 16 + x1];
            }
#pragma unroll
            for (int mt = 0; mt < 4; mt++)
#pragma unroll
                for (int nt = 0; nt < 4; nt++)
                    mma_f16(acc[mt][nt], af[mt][0], af[mt][1], af[mt][2], af[mt][3],
                            bf[nt][0], bf[nt][1]);
        }
        s = s + 1; if (s >= 3) s -= 3;
    }

    float sc[4][2], qc[4][2];
#pragma unroll
    for (int nt = 0; nt < 4; nt++) { sc[nt][0] = sc[nt][1] = qc[nt][0] = qc[nt][1] = 0.f; }

#pragma unroll
    for (int mt = 0; mt < 4; mt++) {
        int r0 = bm + wm + mt * 16 + lr;
        float gate0 = 0.f, gate1 = 0.f;
        if (useCwl) {
            if (r0 < M)     gate0 = (g_scr[IDG_F + r0] != 0.f) ? 1.f : 0.f;
            if (r0 + 8 < M) gate1 = (g_scr[IDG_F + r0 + 8] != 0.f) ? 1.f : 0.f;
        }
#pragma unroll
        for (int nt = 0; nt < 4; nt++) {
            int cc = bn + wn + nt * 8 + 2 * lc;
            if (cc < Nd) {
                float b0 = g_scr[BF_F + cc], b1 = g_scr[BF_F + cc + 1];
                float w0 = useCwl ? g_scr[CWL_F + cc] : 0.f;
                float w1 = useCwl ? g_scr[CWL_F + cc + 1] : 0.f;
                if (r0 < M) {
                    float v0 = acc[mt][nt][0] + b0 + gate0 * w0;
                    float v1 = acc[mt][nt][1] + b1 + gate0 * w1;
                    if (doRelu) { v0 = fmaxf(v0, 0.f); v1 = fmaxf(v1, 0.f); }
                    if (OUTF32) {
                        *reinterpret_cast<float2*>(g_scr + outOff + (size_t)r0 * Nd + cc) =
                            make_float2(v0, v1);
                    } else {
                        *reinterpret_cast<__half2*>(GH + outOff + (size_t)r0 * Nd + cc) =
                            __floats2half2_rn(v0, v1);
                    }
                    sc[nt][0] += v0; qc[nt][0] += v0 * v0;
                    sc[nt][1] += v1; qc[nt][1] += v1 * v1;
                }
                if (r0 + 8 < M) {
                    float v0 = acc[mt][nt][2] + b0 + gate1 * w0;
                    float v1 = acc[mt][nt][3] + b1 + gate1 * w1;
                    if (doRelu) { v0 = fmaxf(v0, 0.f); v1 = fmaxf(v1, 0.f); }
                    if (OUTF32) {
                        *reinterpret_cast<float2*>(g_scr + outOff + (size_t)(r0 + 8) * Nd + cc) =
                            make_float2(v0, v1);
                    } else {
                        *reinterpret_cast<__half2*>(GH + outOff + (size_t)(r0 + 8) * Nd + cc) =
                            __floats2half2_rn(v0, v1);
                    }
                    sc[nt][0] += v0; qc[nt][0] += v0 * v0;
                    sc[nt][1] += v1; qc[nt][1] += v1 * v1;
                }
            }
        }
    }

    if (doBN) {
        __syncthreads();
        float* redS = smem;
        float* redQ = smem + 256;
#pragma unroll
        for (int nt = 0; nt < 4; nt++) {
#pragma unroll
            for (int j = 0; j < 2; j++) {
                float v = sc[nt][j], q = qc[nt][j];
                v += __shfl_xor_sync(0xFFFFFFFFu, v, 4);
                v += __shfl_xor_sync(0xFFFFFFFFu, v, 8);
                v += __shfl_xor_sync(0xFFFFFFFFu, v, 16);
                q += __shfl_xor_sync(0xFFFFFFFFu, q, 4);
                q += __shfl_xor_sync(0xFFFFFFFFu, q, 8);
                q += __shfl_xor_sync(0xFFFFFFFFu, q, 16);
                if (lr == 0) {
                    redS[wid * 32 + nt * 8 + 2 * lc + j] = v;
                    redQ[wid * 32 + nt * 8 + 2 * lc + j] = q;
                }
            }
        }
        __syncthreads();
        if (tid < 128) {
            int wg = tid >> 5, c2 = tid & 31;
            float sv = redS[wg * 32 + c2] + redS[(wg + 4) * 32 + c2];
            float qv = redQ[wg * 32 + c2] + redQ[(wg + 4) * 32 + c2];
            int colG = bn + wg * 32 + c2;
            if (colG < Nd) {
                g_scr[PART_F + (size_t)blockIdx.y * 2048 + colG] = sv;
                g_scr[PART_F + (size_t)blockIdx.y * 2048 + 1024 + colG] = qv;
            }
        }
    }
}

// ================= fp16 dual GEMM, BN=256 wide (layers 3-4) ==================
// 512 threads, 16 warps = 2(M) x 8(N); warp tile 64x32; 3-stage, 24KB/stage.
__global__ __launch_bounds__(512, 1) void gemm_f16w(
    int aOff1, int aOff2, int wtOff,
    int M, int K1, int K2, int Nd, int outOff)
{
    extern __shared__ float smem[];
    uint32_t sbase = (uint32_t)__cvta_generic_to_shared(smem);
    int tid = threadIdx.x, lane = tid & 31, wid = tid >> 5;
    int bm = blockIdx.y * 128, bn = blockIdx.x * 256;
    int wm = (wid >> 3) * 64, wn = (wid & 7) * 32;
    int lr = lane >> 2, lc = lane & 3;
    int KT = K1 + K2;
    int NCH = KT / 32;

    float acc[4][4][4];
#pragma unroll
    for (int i = 0; i < 4; i++)
#pragma unroll
        for (int j = 0; j < 4; j++)
#pragma unroll
            for (int k = 0; k < 4; k++) acc[i][j][k] = 0.0f;

    auto issue = [&](int st, int c) {
        uint32_t aReg = sbase + st * 24576;
        uint32_t bReg = aReg + 8192;
        int ck = c * 32;
        const __half* Asrc;
        int astride, acol;
        if (ck < K1) { Asrc = GH + aOff1; astride = K1; acol = ck; }
        else         { Asrc = GH + aOff2; astride = K2; acol = ck - K1; }
        {
            int idx = tid;                       // 512 A-chunks
            int r = idx >> 2, c16 = idx & 3;
            int ar = bm + r; if (ar >= M) ar = M - 1;
            const void* src = Asrc + (size_t)ar * astride + acol + c16 * 8;
            int w = (c16 * 4) ^ (((r >> 1) & 3) << 2);
            cp16(aReg + (uint32_t)(r * 64 + w * 4), src);
        }
#pragma unroll
        for (int i = 0; i < 2; i++) {            // 1024 B-chunks
            int idx = tid + i * 512;
            int n = idx >> 2, c16 = idx & 3;
            const void* src = GH + wtOff + (size_t)(bn + n) * KT + ck + c16 * 8;
            int w = (c16 * 4) ^ (((n >> 1) & 3) << 2);
            cp16(bReg + (uint32_t)(n * 64 + w * 4), src);
        }
        asm volatile("cp.async.commit_group;\n" ::: "memory");
    };

    issue(0, 0);
    if (NCH > 1) issue(1, 1);
    else asm volatile("cp.async.commit_group;\n" ::: "memory");

    int swz = ((lr >> 1) & 3) << 2;

    int s = 0;
    for (int c = 0; c < NCH; c++) {
        asm volatile("cp.async.wait_group 1;\n" ::: "memory");
        __syncthreads();
        int s2 = s + 2; if (s2 >= 3) s2 -= 3;
        if (c + 2 < NCH) issue(s2, c + 2);
        else asm volatile("cp.async.commit_group;\n" ::: "memory");

        const uint32_t* As = (const uint32_t*)smem + s * 6144;
        const uint32_t* Bs = As + 2048;
#pragma unroll
        for (int ks = 0; ks < 2; ks++) {
            int kb = ks * 8;
            int x0 = (kb + lc) ^ swz, x1 = (kb + lc + 4) ^ swz;
            uint32_t af[4][4], bf[4][2];
#pragma unroll
            for (int mt = 0; mt < 4; mt++) {
                int r = wm + mt * 16 + lr;
                af[mt][0] = As[r * 16 + x0];
                af[mt][1] = As[(r + 8) * 16 + x0];
                af[mt][2] = As[r * 16 + x1];
                af[mt][3] = As[(r + 8) * 16 + x1];
            }
#pragma unroll
            for (int nt = 0; nt < 4; nt++) {
                int n = wn + nt * 8 + lr;
                bf[nt][0] = Bs[n * 16 + x0];
                bf[nt][1] = Bs[n * 16 + x1];
            }
#pragma unroll
            for (int mt = 0; mt < 4; mt++)
#pragma unroll
                for (int nt = 0; nt < 4; nt++)
                    mma_f16(acc[mt][nt], af[mt][0], af[mt][1], af[mt][2], af[mt][3],
                            bf[nt][0], bf[nt][1]);
        }
        s = s + 1; if (s >= 3) s -= 3;
    }

    // ---- epilogue (always ReLU + fp16 out + cwl + BN) ----
    float sc[4][2], qc[4][2];
#pragma unroll
    for (int nt = 0; nt < 4; nt++) { sc[nt][0] = sc[nt][1] = qc[nt][0] = qc[nt][1] = 0.f; }

#pragma unroll
    for (int mt = 0; mt < 4; mt++) {
        int r0 = bm + wm + mt * 16 + lr;
        float gate0 = 0.f, gate1 = 0.f;
        if (r0 < M)     gate0 = (g_scr[IDG_F + r0] != 0.f) ? 1.f : 0.f;
        if (r0 + 8 < M) gate1 = (g_scr[IDG_F + r0 + 8] != 0.f) ? 1.f : 0.f;
#pragma unroll
        for (int nt = 0; nt < 4; nt++) {
            int cc = bn + wn + nt * 8 + 2 * lc;
            float b0 = g_scr[BF_F + cc], b1 = g_scr[BF_F + cc + 1];
            float w0 = g_scr[CWL_F + cc], w1 = g_scr[CWL_F + cc + 1];
            if (r0 < M) {
                float v0 = fmaxf(acc[mt][nt][0] + b0 + gate0 * w0, 0.f);
                float v1 = fmaxf(acc[mt][nt][1] + b1 + gate0 * w1, 0.f);
                *reinterpret_cast<__half2*>(GH + outOff + (size_t)r0 * Nd + cc) =
                    __floats2half2_rn(v0, v1);
                sc[nt][0] += v0; qc[nt][0] += v0 * v0;
                sc[nt][1] += v1; qc[nt][1] += v1 * v1;
            }
            if (r0 + 8 < M) {
                float v0 = fmaxf(acc[mt][nt][2] + b0 + gate1 * w0, 0.f);
                float v1 = fmaxf(acc[mt][nt][3] + b1 + gate1 * w1, 0.f);
                *reinterpret_cast<__half2*>(GH + outOff + (size_t)(r0 + 8) * Nd + cc) =
                    __floats2half2_rn(v0, v1);
                sc[nt][0] += v0; qc[nt][0] += v0 * v0;
                sc[nt][1] += v1; qc[nt][1] += v1 * v1;
            }
        }
    }

    __syncthreads();
    float* redS = smem;          // [16][32]
    float* redQ = smem + 512;
#pragma unroll
    for (int nt = 0; nt < 4; nt++) {
#pragma unroll
        for (int j = 0; j < 2; j++) {
            float v = sc[nt][j], q = qc[nt][j];
            v += __shfl_xor_sync(0xFFFFFFFFu, v, 4);
            v += __shfl_xor_sync(0xFFFFFFFFu, v, 8);
            v += __shfl_xor_sync(0xFFFFFFFFu, v, 16);
            q += __shfl_xor_sync(0xFFFFFFFFu, q, 4);
            q += __shfl_xor_sync(0xFFFFFFFFu, q, 8);
            q += __shfl_xor_sync(0xFFFFFFFFu, q, 16);
            if (lr == 0) {
                redS[wid * 32 + nt * 8 + 2 * lc + j] = v;
                redQ[wid * 32 + nt * 8 + 2 * lc + j] = q;
            }
        }
    }
    __syncthreads();
    if (tid < 256) {
        int wg = tid >> 5, c2 = tid & 31;
        float sv = redS[wg * 32 + c2] + redS[(wg + 8) * 32 + c2];
        float qv = redQ[wg * 32 + c2] + redQ[(wg + 8) * 32 + c2];
        int colG = bn + wg * 32 + c2;
        g_scr[PART_F + (size_t)blockIdx.y * 2048 + colG] = sv;
        g_scr[PART_F + (size_t)blockIdx.y * 2048 + 1024 + colG] = qv;
    }
}

// ================= BN partial reduce -> (a, c) ===============================
__global__ void bn_reduce(int d, const float* __restrict__ g, const float* __restrict__ be) {
    int colI = blockIdx.x * blockDim.x + threadIdx.x;
    if (colI >= d) return;
    float s = 0.f, q = 0.f;
    for (int p = 0; p < NYB; p++) {
        s += g_scr[PART_F + (size_t)p * 2048 + colI];
        q += g_scr[PART_F + (size_t)p * 2048 + 1024 + colI];
    }
    float invM = 1.0f / (float)N_NODES;
    float mean = s * invM;
    float var = q * invM - mean * mean;
    float a = g[colI] * rsqrtf(var + BN_EPS);
    g_scr[ST_F + colI] = a;
    g_scr[ST_F + MAXD + colI] = be[colI] - mean * a;
}

// ================= transposed fp16 weight fold ===============================
__global__ void tfold16(const float* __restrict__ Wl, const float* __restrict__ Wr,
                        int din, int dout, int KT, int mode, int useScale) {
    __shared__ float tile[32][33];
    int k0 = blockIdx.x * 32, n0 = blockIdx.y * 32;
    int tx = threadIdx.x, ty = threadIdx.y;
#pragma unroll
    for (int j = 0; j < 4; j++) {
        int k = k0 + ty + j * 8;
        float w;
        if (mode == 0) {
            w = (k < din) ? Wl[(size_t)k * dout + n0 + tx]
                          : Wr[(size_t)(k - din) * dout + n0 + tx];
        } else {
            int n = n0 + tx;
            w = (n < 40) ? Wl[(size_t)k * 40 + n]
                         : ((n < 80) ? Wr[(size_t)k * 40 + n - 40] : 0.f);
        }
        tile[ty + j * 8][tx] = w;
    }
    __syncthreads();
#pragma unroll
    for (int j = 0; j < 4; j++) {
        int n = n0 + ty + j * 8;
        int k = k0 + tx;
        float a = 1.f;
        if (useScale) {
            int kk = (mode == 0 && k >= din) ? k - din : k;
            a = g_scr[ST_F + kk];
        }
        GH[HWT_H + (size_t)n * KT + k] = __float2half(a * tile[tx][ty + j * 8]);
    }
}

__global__ void cfold(const float* __restrict__ Wl, const float* __restrict__ Wr,
                      const float* __restrict__ b, int din, int dout) {
    int n = blockIdx.x * blockDim.x + threadIdx.x;
    if (n >= dout) return;
    float sl = 0.f, sw = 0.f;
    for (int k = 0; k < din; k++) {
        float c = g_scr[ST_F + MAXD + k];
        sl += c * Wl[(size_t)k * dout + n];
        sw += c * Wr[(size_t)k * dout + n];
    }
    g_scr[CWL_F + n] = sl;
    g_scr[BF_F + n] = b[n] + sw;
}

__global__ void cfold5(const float* __restrict__ Wl, const float* __restrict__ Wr,
                       const float* __restrict__ b) {
    int n = threadIdx.x;
    if (n >= 40) return;
    float sl = 0.f, sw = 0.f;
    for (int k = 0; k < 1024; k++) {
        float c = g_scr[ST_F + MAXD + k];
        sl += c * Wl[(size_t)k * 40 + n];
        sw += c * Wr[(size_t)k * 40 + n];
    }
    g_scr[CWL_F + n] = sl;
    g_scr[BF_F + n] = 0.f;
    g_scr[BF_F + 40 + n] = b[n] + sw;
}

__global__ void biascopy(const float* __restrict__ b, int d) {
    int n = blockIdx.x * blockDim.x + threadIdx.x;
    if (n < d) { g_scr[BF_F + n] = b[n]; g_scr[CWL_F + n] = 0.f; }
}

// ================= final: combine + log_softmax ==============================
__global__ void final_kernel(float* __restrict__ out, int M) {
    int node = (blockIdx.x * blockDim.x + threadIdx.x) >> 5;
    int lane = threadIdx.x & 31;
    if (node >= M) return;
    float gate = (g_scr[IDG_F + node] != 0.f) ? 1.f : 0.f;
    long long zb = (long long)node * 80;
    long long ab = (long long)node * 40;
    int c1 = lane + 32;
    bool has1 = c1 < 40;
    float a0 = g_scr[A40_F + ab + lane] + gate * g_scr[CWL_F + lane]
             + g_scr[ZW_F + zb + 40 + lane];
    float a1 = has1 ? (g_scr[A40_F + ab + c1] + gate * g_scr[CWL_F + c1]
                       + g_scr[ZW_F + zb + 40 + c1])
                    : -INFINITY;
    float mx = fmaxf(a0, a1);
#pragma unroll
    for (int o = 16; o; o >>= 1) mx = fmaxf(mx, __shfl_xor_sync(0xFFFFFFFFu, mx, o));
    float e = expf(a0 - mx) + (has1 ? expf(a1 - mx) : 0.f);
#pragma unroll
    for (int o = 16; o; o >>= 1) e += __shfl_xor_sync(0xFFFFFFFFu, e, o);
    float l = logf(e);
    out[(long long)node * 40 + lane] = a0 - mx - l;
    if (has1) out[(long long)node * 40 + c1] = a1 - mx - l;
}

// ================= launch (single stream, capture-safe) ======================
extern "C" void kernel_launch(void* const* d_in, const int* in_sizes, int n_in,
                              void* d_out, int out_size) {
    const int N = N_NODES, E = N_EDGES;
    const float* x = (const float*)d_in[0];
    const int* ei = (const int*)d_in[1];
    const int* src = ei;
    const int* dst = ei + E;

    const float *Wl[5], *Wr[5], *bb[5], *gg[4], *bea[4];
    int idx = 2;
    for (int i = 0; i < 5; i++) {
        Wl[i] = (const float*)d_in[idx++];
        Wr[i] = (const float*)d_in[idx++];
        bb[i] = (const float*)d_in[idx++];
    }
    for (int i = 0; i < 4; i++) {
        gg[i] = (const float*)d_in[idx++];
        bea[i] = (const float*)d_in[idx++];
    }

    const int SMG = 49152;    // 3 x 16KB (narrow)
    const int SMW = 73728;    // 3 x 24KB (wide)
    cudaFuncSetAttribute(gemm_f16<0>, cudaFuncAttributeMaxDynamicSharedMemorySize, SMG);
    cudaFuncSetAttribute(gemm_f16<1>, cudaFuncAttributeMaxDynamicSharedMemorySize, SMG);
    cudaFuncSetAttribute(gemm_f16w, cudaFuncAttributeMaxDynamicSharedMemorySize, SMW);

    int* di = (int*)d_out;
    int* deg = di;
    int* off = di + 50000;
    int* cur = di + 100064;
    int* col = di + 150080;
    int* bsum = di + 550080;

    zero_ints<<<(150080 + 255) / 256, 256>>>(di, 150080);
    hist_kernel<<<(E + 255) / 256, 256>>>(dst, deg, E);
    scan1<<<13, 1024>>>(deg, off, bsum);
    scan2<<<1, 32>>>(bsum);
    scan3<<<13, 1024>>>(off, bsum);
    invdeg_kernel<<<(N + 255) / 256, 256>>>(deg);
    csr_scatter<<<(E + 255) / 256, 256>>>(src, dst, off, cur, col, E);

    xconv<<<(N * 32 + 255) / 256, 256>>>(x);

    int gb = (N * 32 + 255) / 256;

    // ---- layer 1: 128 -> 128 ----
    tfold16<<<dim3(8, 4), dim3(32, 8)>>>(Wl[0], Wr[0], 128, 128, 256, 0, 0);
    biascopy<<<1, 128>>>(bb[0], 128);
    gather16<1><<<gb, 256>>>(HXIN_H, HAGG_H, off, col, 32);
    gemm_f16<0><<<dim3(1, NYB), 256, SMG>>>(HAGG_H, HXIN_H, HWT_H,
                                            N, 128, 128, 128, 0, HY_H, 1, 1);
    bn_reduce<<<1, 128>>>(128, gg[0], bea[0]);

    // ---- layer 2: 128 -> 256 ----
    tfold16<<<dim3(8, 8), dim3(32, 8)>>>(Wl[1], Wr[1], 128, 256, 256, 0, 1);
    cfold<<<1, 256>>>(Wl[1], Wr[1], bb[1], 128, 256);
    gather16<1><<<gb, 256>>>(HY_H, HAGG_H, off, col, 32);
    gemm_f16<0><<<dim3(2, NYB), 256, SMG>>>(HAGG_H, HY_H, HWT_H,
                                            N, 128, 128, 256, 1, HX_H, 1, 1);
    bn_reduce<<<1, 256>>>(256, gg[1], bea[1]);

    // ---- layer 3: 256 -> 512 (wide) ----
    tfold16<<<dim3(16, 16), dim3(32, 8)>>>(Wl[2], Wr[2], 256, 512, 512, 0, 1);
    cfold<<<2, 256>>>(Wl[2], Wr[2], bb[2], 256, 512);
    gather16<2><<<gb, 256>>>(HX_H, HAGG_H, off, col, 64);
    gemm_f16w<<<dim3(2, NYB), 512, SMW>>>(HAGG_H, HX_H, HWT_H,
                                          N, 256, 256, 512, HY_H);
    bn_reduce<<<2, 256>>>(512, gg[2], bea[2]);

    // ---- layer 4: 512 -> 1024 (wide) ----
    tfold16<<<dim3(32, 32), dim3(32, 8)>>>(Wl[3], Wr[3], 512, 1024, 1024, 0, 1);
    cfold<<<4, 256>>>(Wl[3], Wr[3], bb[3], 512, 1024);
    gather16<4><<<gb, 256>>>(HY_H, HAGG_H, off, col, 128);
    gemm_f16w<<<dim3(4, NYB), 512, SMW>>>(HAGG_H, HY_H, HWT_H,
                                          N, 512, 512, 1024, HX_H);
    bn_reduce<<<4, 256>>>(1024, gg[3], bea[3]);

    // ---- layer 5: 1024 -> 80 (z|w colsplit, padded to 128), fp32 out ----
    tfold16<<<dim3(32, 4), dim3(32, 8)>>>(Wl[4], Wr[4], 1024, 128, 1024, 1, 1);
    cfold5<<<1, 64>>>(Wl[4], Wr[4], bb[4]);
    gemm_f16<1><<<dim3(1, NYB), 256, SMG>>>(HAGG_H, HX_H, HWT_H,
                                            N, 0, 1024, 80, 0, ZW_F, 0, 0);
    gather40<<<gb, 256>>>(off, col);

    final_kernel<<<gb, 256>>>((float*)d_out, N);
}

// round 14
// speedup vs baseline: 1.1041x; 1.1041x over previous
#include <cuda_runtime.h>
#include <cuda_fp16.h>
#include <stdlib.h>
#include <math.h>
#include <stdint.h>

__attribute__((constructor)) static void _force_eager_module_load() {
    setenv("CUDA_MODULE_LOADING", "EAGER", 1);
}

#define N_NODES 50000
#define N_EDGES 400000
#define MAXD 1024
#define BN_EPS 1e-5f
#define NYB 391   // ceil(50000/128)

// ---- consolidated scratch (float units; halves view via GH) ------------------
#define HX_H    0            // N*1024 halves (big ping)
#define HY_H    51200000     // N*512 halves (pong)
#define HAGG_H  76800000     // N*512 halves (agg)
#define HXIN_H  102400000    // N*128 halves (x fp16)
#define HWT_H   108800000    // transposed fp16 weights
#define ZW_F    55500000     // N*80 fp32 (layer-5 z|w)
#define A40_F   59500000     // N*40 fp32
#define IDG_F   61500000
#define ST_F    61550080     // a at +0, c at +MAXD
#define PART_F  61552128     // NYB x 2048
#define BF_F    62352896
#define CWL_F   62354944
#define SCR_TOTAL 62356224
__device__ __align__(256) float g_scr[SCR_TOTAL];
#define GH ((__half*)g_scr)

// ================= CSR build (atomics only in d_out) =========================
__global__ void zero_ints(int* __restrict__ p, int n) {
    int i = blockIdx.x * blockDim.x + threadIdx.x;
    if (i < n) p[i] = 0;
}

__global__ void hist_kernel(const int* __restrict__ dst, int* __restrict__ deg, int E) {
    int i = blockIdx.x * blockDim.x + threadIdx.x;
    if (i < E) atomicAdd(&deg[dst[i]], 1);
}

__global__ void scan1(const int* __restrict__ deg, int* __restrict__ off, int* __restrict__ bsum) {
    __shared__ int sh[1024];
    int tid = threadIdx.x;
    int base = blockIdx.x * 4096 + tid * 4;
    int v0 = 0, v1 = 0, v2 = 0, v3 = 0;
    if (base + 3 < N_NODES) {
        int4 v = *(const int4*)(deg + base);
        v0 = v.x; v1 = v.y; v2 = v.z; v3 = v.w;
    } else {
        if (base + 0 < N_NODES) v0 = deg[base + 0];
        if (base + 1 < N_NODES) v1 = deg[base + 1];
        if (base + 2 < N_NODES) v2 = deg[base + 2];
        if (base + 3 < N_NODES) v3 = deg[base + 3];
    }
    int s = v0 + v1 + v2 + v3;
    sh[tid] = s;
    __syncthreads();
    for (int o = 1; o < 1024; o <<= 1) {
        int t = (tid >= o) ? sh[tid - o] : 0;
        __syncthreads();
        sh[tid] += t;
        __syncthreads();
    }
    int ex = sh[tid] - s;
    if (base + 0 < N_NODES) off[base + 0] = ex;
    if (base + 1 < N_NODES) off[base + 1] = ex + v0;
    if (base + 2 < N_NODES) off[base + 2] = ex + v0 + v1;
    if (base + 3 < N_NODES) off[base + 3] = ex + v0 + v1 + v2;
    if (tid == 1023) bsum[blockIdx.x] = sh[1023];
}

__global__ void scan2(int* __restrict__ bsum) {
    if (threadIdx.x == 0) {
        int run = 0;
        for (int i = 0; i < 13; i++) { int v = bsum[i]; bsum[i] = run; run += v; }
        bsum[13] = run;
    }
}

__global__ void scan3(int* __restrict__ off, const int* __restrict__ bsum) {
    int tid = threadIdx.x;
    int add = bsum[blockIdx.x];
    int base = blockIdx.x * 4096 + tid * 4;
#pragma unroll
    for (int j = 0; j < 4; j++)
        if (base + j < N_NODES) off[base + j] += add;
    if (blockIdx.x == 0 && tid == 0) off[N_NODES] = bsum[13];
}

__global__ void invdeg_kernel(const int* __restrict__ deg) {
    int i = blockIdx.x * blockDim.x + threadIdx.x;
    if (i < N_NODES) g_scr[IDG_F + i] = (deg[i] > 0) ? (1.0f / (float)deg[i]) : 0.0f;
}

__global__ void csr_scatter(const int* __restrict__ src, const int* __restrict__ dst,
                            const int* __restrict__ off, int* __restrict__ cur,
                            int* __restrict__ col, int E) {
    int e = blockIdx.x * blockDim.x + threadIdx.x;
    if (e >= E) return;
    int d = dst[e];
    int p = atomicAdd(&cur[d], 1);
    col[off[d] + p] = src[e];
}

// ================= x -> fp16 ==================================================
__global__ void xconv(const float* __restrict__ x) {
    int i = blockIdx.x * blockDim.x + threadIdx.x;
    if (i < N_NODES * 32) {
        float4 v = ((const float4*)x)[i];
        __half2* o = (__half2*)(GH + HXIN_H);
        o[2 * i] = __floats2half2_rn(v.x, v.y);
        o[2 * i + 1] = __floats2half2_rn(v.z, v.w);
    }
}

// ================= gather-mean fp16 (warp per node) ==========================
template <int NU>
__global__ void gather16(int inOffH, int outOffH,
                         const int* __restrict__ off, const int* __restrict__ col,
                         int d4) {
    const uint2* base = (const uint2*)(GH + inOffH);
    uint2* out = (uint2*)(GH + outOffH);
    int node = (blockIdx.x * blockDim.x + threadIdx.x) >> 5;
    int lane = threadIdx.x & 31;
    if (node >= N_NODES) return;
    int s = off[node], e = off[node + 1];
    float sdeg = g_scr[IDG_F + node];
    float2 acc[NU][2];
#pragma unroll
    for (int i = 0; i < NU; i++) {
        acc[i][0] = make_float2(0.f, 0.f);
        acc[i][1] = make_float2(0.f, 0.f);
    }
    for (int j = s; j < e; j++) {
        const uint2* row = base + (size_t)col[j] * d4;
#pragma unroll
        for (int i = 0; i < NU; i++) {
            uint2 v = row[lane + 32 * i];
            uint32_t ux = v.x, uy = v.y;
            float2 f0 = __half22float2(*reinterpret_cast<__half2*>(&ux));
            float2 f1 = __half22float2(*reinterpret_cast<__half2*>(&uy));
            acc[i][0].x += f0.x; acc[i][0].y += f0.y;
            acc[i][1].x += f1.x; acc[i][1].y += f1.y;
        }
    }
    uint2* orow = out + (size_t)node * d4;
#pragma unroll
    for (int i = 0; i < NU; i++) {
        __half2 h0 = __floats2half2_rn(acc[i][0].x * sdeg, acc[i][0].y * sdeg);
        __half2 h1 = __floats2half2_rn(acc[i][1].x * sdeg, acc[i][1].y * sdeg);
        uint2 v;
        v.x = *reinterpret_cast<uint32_t*>(&h0);
        v.y = *reinterpret_cast<uint32_t*>(&h1);
        orow[lane + 32 * i] = v;
    }
}

// ================= gather-mean fp32 for layer-5 z (40 cols) ==================
__global__ void gather40(const int* __restrict__ off, const int* __restrict__ col) {
    const float4* base = (const float4*)(g_scr + ZW_F);
    float4* out = (float4*)(g_scr + A40_F);
    int node = (blockIdx.x * blockDim.x + threadIdx.x) >> 5;
    int lane = threadIdx.x & 31;
    if (node >= N_NODES) return;
    int s = off[node], e = off[node + 1];
    float sdeg = g_scr[IDG_F + node];
    float4 acc = make_float4(0.f, 0.f, 0.f, 0.f);
    if (lane < 10) {
        for (int j = s; j < e; j++) {
            float4 v = base[(size_t)col[j] * 20 + lane];
            acc.x += v.x; acc.y += v.y; acc.z += v.z; acc.w += v.w;
        }
        acc.x *= sdeg; acc.y *= sdeg; acc.z *= sdeg; acc.w *= sdeg;
        out[(size_t)node * 10 + lane] = acc;
    }
}

// ================= helpers ===================================================
__device__ __forceinline__ void mma_f16(float c[4], uint32_t a0, uint32_t a1,
                                        uint32_t a2, uint32_t a3,
                                        uint32_t b0, uint32_t b1) {
    asm volatile(
        "mma.sync.aligned.m16n8k16.row.col.f32.f16.f16.f32 "
        "{%0,%1,%2,%3}, {%4,%5,%6,%7}, {%8,%9}, {%0,%1,%2,%3};"
        : "+f"(c[0]), "+f"(c[1]), "+f"(c[2]), "+f"(c[3])
        : "r"(a0), "r"(a1), "r"(a2), "r"(a3), "r"(b0), "r"(b1));
}

__device__ __forceinline__ void cp16(uint32_t dst, const void* src) {
    asm volatile("cp.async.cg.shared.global [%0], [%1], 16;\n"
                 :: "r"(dst), "l"(src) : "memory");
}

__device__ __forceinline__ void ldm4(uint32_t& r0, uint32_t& r1, uint32_t& r2,
                                     uint32_t& r3, uint32_t addr) {
    asm volatile("ldmatrix.sync.aligned.m8n8.x4.shared.b16 {%0,%1,%2,%3}, [%4];"
                 : "=r"(r0), "=r"(r1), "=r"(r2), "=r"(r3) : "r"(addr));
}

// ================= fp16 dual GEMM, BN=128, ldmatrix fragments ================
// D[m,n] = sum_k A[m,k] * WT[n,k] + bias[n] (+ gate_m*cwl[n]) [ReLU]
// Tile 128x128, BK=32 halves, 3-stage cp.async, occupancy 2.
template <int OUTF32>
__global__ __launch_bounds__(256, 2) void gemm_f16(
    int aOff1, int aOff2, int wtOff,
    int M, int K1, int K2, int Nd,
    int useCwl, int outOff, int doRelu, int doBN)
{
    extern __shared__ float smem[];
    uint32_t sbase = (uint32_t)__cvta_generic_to_shared(smem);
    int tid = threadIdx.x, lane = tid & 31, wid = tid >> 5;
    int bm = blockIdx.y * 128, bn = blockIdx.x * 128;
    int wm = (wid >> 2) * 64, wn = (wid & 3) * 32;
    int lr = lane >> 2, lc = lane & 3;
    int KT = K1 + K2;
    int NCH = KT / 32;

    // ldmatrix per-lane constants (see derivation: swizzle invariant under
    // +8/+16 row offsets, so one constant serves A and B)
    int l7 = lane & 7;
    int lSwz = ((l7 >> 1) & 3) << 2;                    // pair-unit swizzle
    int aRow = l7 + ((lane >> 3) & 1) * 8;              // + wm + mt*16
    int aG = 4 * (lane >> 4);                           // 0 or 4 (pair units)
    int bRow = l7 + ((lane >> 4) & 1) * 8;              // + wn + t*16
    int bG = 4 * ((lane >> 3) & 1);

    float acc[4][4][4];
#pragma unroll
    for (int i = 0; i < 4; i++)
#pragma unroll
        for (int j = 0; j < 4; j++)
#pragma unroll
            for (int k = 0; k < 4; k++) acc[i][j][k] = 0.0f;

    auto issue = [&](int st, int c) {
        uint32_t aReg = sbase + st * 16384;
        uint32_t bReg = aReg + 8192;
        int ck = c * 32;
        const __half* Asrc;
        int astride, acol;
        if (ck < K1) { Asrc = GH + aOff1; astride = K1; acol = ck; }
        else         { Asrc = GH + aOff2; astride = K2; acol = ck - K1; }
#pragma unroll
        for (int i = 0; i < 2; i++) {
            int idx = tid + i * 256;
            int r = idx >> 2, c16 = idx & 3;
            int ar = bm + r; if (ar >= M) ar = M - 1;
            const void* src = Asrc + (size_t)ar * astride + acol + c16 * 8;
            int w = (c16 * 4) ^ (((r >> 1) & 3) << 2);
            cp16(aReg + (uint32_t)(r * 64 + w * 4), src);
        }
#pragma unroll
        for (int i = 0; i < 2; i++) {
            int idx = tid + i * 256;
            int n = idx >> 2, c16 = idx & 3;
            const void* src = GH + wtOff + (size_t)(bn + n) * KT + ck + c16 * 8;
            int w = (c16 * 4) ^ (((n >> 1) & 3) << 2);
            cp16(bReg + (uint32_t)(n * 64 + w * 4), src);
        }
        asm volatile("cp.async.commit_group;\n" ::: "memory");
    };

    issue(0, 0);
    if (NCH > 1) issue(1, 1);
    else asm volatile("cp.async.commit_group;\n" ::: "memory");

    int swz = ((lr >> 1) & 3) << 2;   // epilogue-free; kept for clarity
    (void)swz; (void)lc;

    int s = 0;
    for (int c = 0; c < NCH; c++) {
        asm volatile("cp.async.wait_group 1;\n" ::: "memory");
        __syncthreads();
        int s2 = s + 2; if (s2 >= 3) s2 -= 3;
        if (c + 2 < NCH) issue(s2, c + 2);
        else asm volatile("cp.async.commit_group;\n" ::: "memory");

        uint32_t aBase = sbase + s * 16384;
        uint32_t bBase = aBase + 8192;
#pragma unroll
        for (int ks = 0; ks < 2; ks++) {
            uint32_t af[4][4], bf[4][2];
            int gA = (8 * ks + aG) ^ lSwz;   // pair-unit column offset
            int gB = (8 * ks + bG) ^ lSwz;
#pragma unroll
            for (int mt = 0; mt < 4; mt++) {
                int row = wm + mt * 16 + aRow;
                ldm4(af[mt][0], af[mt][1], af[mt][2], af[mt][3],
                     aBase + (uint32_t)((row * 16 + gA) * 4));
            }
#pragma unroll
            for (int t = 0; t < 2; t++) {
                int n = wn + t * 16 + bRow;
                ldm4(bf[2 * t][0], bf[2 * t][1], bf[2 * t + 1][0], bf[2 * t + 1][1],
                     bBase + (uint32_t)((n * 16 + gB) * 4));
            }
#pragma unroll
            for (int mt = 0; mt < 4; mt++)
#pragma unroll
                for (int nt = 0; nt < 4; nt++)
                    mma_f16(acc[mt][nt], af[mt][0], af[mt][1], af[mt][2], af[mt][3],
                            bf[nt][0], bf[nt][1]);
        }
        s = s + 1; if (s >= 3) s -= 3;
    }

    // ---- epilogue ----
    float sc[4][2], qc[4][2];
#pragma unroll
    for (int nt = 0; nt < 4; nt++) { sc[nt][0] = sc[nt][1] = qc[nt][0] = qc[nt][1] = 0.f; }

#pragma unroll
    for (int mt = 0; mt < 4; mt++) {
        int r0 = bm + wm + mt * 16 + lr;
        float gate0 = 0.f, gate1 = 0.f;
        if (useCwl) {
            if (r0 < M)     gate0 = (g_scr[IDG_F + r0] != 0.f) ? 1.f : 0.f;
            if (r0 + 8 < M) gate1 = (g_scr[IDG_F + r0 + 8] != 0.f) ? 1.f : 0.f;
        }
#pragma unroll
        for (int nt = 0; nt < 4; nt++) {
            int cc = bn + wn + nt * 8 + 2 * lc;
            if (cc < Nd) {
                float b0 = g_scr[BF_F + cc], b1 = g_scr[BF_F + cc + 1];
                float w0 = useCwl ? g_scr[CWL_F + cc] : 0.f;
                float w1 = useCwl ? g_scr[CWL_F + cc + 1] : 0.f;
                if (r0 < M) {
                    float v0 = acc[mt][nt][0] + b0 + gate0 * w0;
                    float v1 = acc[mt][nt][1] + b1 + gate0 * w1;
                    if (doRelu) { v0 = fmaxf(v0, 0.f); v1 = fmaxf(v1, 0.f); }
                    if (OUTF32) {
                        *reinterpret_cast<float2*>(g_scr + outOff + (size_t)r0 * Nd + cc) =
                            make_float2(v0, v1);
                    } else {
                        *reinterpret_cast<__half2*>(GH + outOff + (size_t)r0 * Nd + cc) =
                            __floats2half2_rn(v0, v1);
                    }
                    sc[nt][0] += v0; qc[nt][0] += v0 * v0;
                    sc[nt][1] += v1; qc[nt][1] += v1 * v1;
                }
                if (r0 + 8 < M) {
                    float v0 = acc[mt][nt][2] + b0 + gate1 * w0;
                    float v1 = acc[mt][nt][3] + b1 + gate1 * w1;
                    if (doRelu) { v0 = fmaxf(v0, 0.f); v1 = fmaxf(v1, 0.f); }
                    if (OUTF32) {
                        *reinterpret_cast<float2*>(g_scr + outOff + (size_t)(r0 + 8) * Nd + cc) =
                            make_float2(v0, v1);
                    } else {
                        *reinterpret_cast<__half2*>(GH + outOff + (size_t)(r0 + 8) * Nd + cc) =
                            __floats2half2_rn(v0, v1);
                    }
                    sc[nt][0] += v0; qc[nt][0] += v0 * v0;
                    sc[nt][1] += v1; qc[nt][1] += v1 * v1;
                }
            }
        }
    }

    if (doBN) {
        __syncthreads();
        float* redS = smem;
        float* redQ = smem + 256;
#pragma unroll
        for (int nt = 0; nt < 4; nt++) {
#pragma unroll
            for (int j = 0; j < 2; j++) {
                float v = sc[nt][j], q = qc[nt][j];
                v += __shfl_xor_sync(0xFFFFFFFFu, v, 4);
                v += __shfl_xor_sync(0xFFFFFFFFu, v, 8);
                v += __shfl_xor_sync(0xFFFFFFFFu, v, 16);
                q += __shfl_xor_sync(0xFFFFFFFFu, q, 4);
                q += __shfl_xor_sync(0xFFFFFFFFu, q, 8);
                q += __shfl_xor_sync(0xFFFFFFFFu, q, 16);
                if (lr == 0) {
                    redS[wid * 32 + nt * 8 + 2 * lc + j] = v;
                    redQ[wid * 32 + nt * 8 + 2 * lc + j] = q;
                }
            }
        }
        __syncthreads();
        if (tid < 128) {
            int wg = tid >> 5, c2 = tid & 31;
            float sv = redS[wg * 32 + c2] + redS[(wg + 4) * 32 + c2];
            float qv = redQ[wg * 32 + c2] + redQ[(wg + 4) * 32 + c2];
            int colG = bn + wg * 32 + c2;
            if (colG < Nd) {
                g_scr[PART_F + (size_t)blockIdx.y * 2048 + colG] = sv;
                g_scr[PART_F + (size_t)blockIdx.y * 2048 + 1024 + colG] = qv;
            }
        }
    }
}

// ================= BN partial reduce -> (a, c) ===============================
__global__ void bn_reduce(int d, const float* __restrict__ g, const float* __restrict__ be) {
    int colI = blockIdx.x * blockDim.x + threadIdx.x;
    if (colI >= d) return;
    float s = 0.f, q = 0.f;
    for (int p = 0; p < NYB; p++) {
        s += g_scr[PART_F + (size_t)p * 2048 + colI];
        q += g_scr[PART_F + (size_t)p * 2048 + 1024 + colI];
    }
    float invM = 1.0f / (float)N_NODES;
    float mean = s * invM;
    float var = q * invM - mean * mean;
    float a = g[colI] * rsqrtf(var + BN_EPS);
    g_scr[ST_F + colI] = a;
    g_scr[ST_F + MAXD + colI] = be[colI] - mean * a;
}

// ================= transposed fp16 weight fold ===============================
__global__ void tfold16(const float* __restrict__ Wl, const float* __restrict__ Wr,
                        int din, int dout, int KT, int mode, int useScale) {
    __shared__ float tile[32][33];
    int k0 = blockIdx.x * 32, n0 = blockIdx.y * 32;
    int tx = threadIdx.x, ty = threadIdx.y;
#pragma unroll
    for (int j = 0; j < 4; j++) {
        int k = k0 + ty + j * 8;
        float w;
        if (mode == 0) {
            w = (k < din) ? Wl[(size_t)k * dout + n0 + tx]
                          : Wr[(size_t)(k - din) * dout + n0 + tx];
        } else {
            int n = n0 + tx;
            w = (n < 40) ? Wl[(size_t)k * 40 + n]
                         : ((n < 80) ? Wr[(size_t)k * 40 + n - 40] : 0.f);
        }
        tile[ty + j * 8][tx] = w;
    }
    __syncthreads();
#pragma unroll
    for (int j = 0; j < 4; j++) {
        int n = n0 + ty + j * 8;
        int k = k0 + tx;
        float a = 1.f;
        if (useScale) {
            int kk = (mode == 0 && k >= din) ? k - din : k;
            a = g_scr[ST_F + kk];
        }
        GH[HWT_H + (size_t)n * KT + k] = __float2half(a * tile[tx][ty + j * 8]);
    }
}

__global__ void cfold(const float* __restrict__ Wl, const float* __restrict__ Wr,
                      const float* __restrict__ b, int din, int dout) {
    int n = blockIdx.x * blockDim.x + threadIdx.x;
    if (n >= dout) return;
    float sl = 0.f, sw = 0.f;
    for (int k = 0; k < din; k++) {
        float c = g_scr[ST_F + MAXD + k];
        sl += c * Wl[(size_t)k * dout + n];
        sw += c * Wr[(size_t)k * dout + n];
    }
    g_scr[CWL_F + n] = sl;
    g_scr[BF_F + n] = b[n] + sw;
}

__global__ void cfold5(const float* __restrict__ Wl, const float* __restrict__ Wr,
                       const float* __restrict__ b) {
    int n = threadIdx.x;
    if (n >= 40) return;
    float sl = 0.f, sw = 0.f;
    for (int k = 0; k < 1024; k++) {
        float c = g_scr[ST_F + MAXD + k];
        sl += c * Wl[(size_t)k * 40 + n];
        sw += c * Wr[(size_t)k * 40 + n];
    }
    g_scr[CWL_F + n] = sl;
    g_scr[BF_F + n] = 0.f;
    g_scr[BF_F + 40 + n] = b[n] + sw;
}

__global__ void biascopy(const float* __restrict__ b, int d) {
    int n = blockIdx.x * blockDim.x + threadIdx.x;
    if (n < d) { g_scr[BF_F + n] = b[n]; g_scr[CWL_F + n] = 0.f; }
}

// ================= final: combine + log_softmax ==============================
__global__ void final_kernel(float* __restrict__ out, int M) {
    int node = (blockIdx.x * blockDim.x + threadIdx.x) >> 5;
    int lane = threadIdx.x & 31;
    if (node >= M) return;
    float gate = (g_scr[IDG_F + node] != 0.f) ? 1.f : 0.f;
    long long zb = (long long)node * 80;
    long long ab = (long long)node * 40;
    int c1 = lane + 32;
    bool has1 = c1 < 40;
    float a0 = g_scr[A40_F + ab + lane] + gate * g_scr[CWL_F + lane]
             + g_scr[ZW_F + zb + 40 + lane];
    float a1 = has1 ? (g_scr[A40_F + ab + c1] + gate * g_scr[CWL_F + c1]
                       + g_scr[ZW_F + zb + 40 + c1])
                    : -INFINITY;
    float mx = fmaxf(a0, a1);
#pragma unroll
    for (int o = 16; o; o >>= 1) mx = fmaxf(mx, __shfl_xor_sync(0xFFFFFFFFu, mx, o));
    float e = expf(a0 - mx) + (has1 ? expf(a1 - mx) : 0.f);
#pragma unroll
    for (int o = 16; o; o >>= 1) e += __shfl_xor_sync(0xFFFFFFFFu, e, o);
    float l = logf(e);
    out[(long long)node * 40 + lane] = a0 - mx - l;
    if (has1) out[(long long)node * 40 + c1] = a1 - mx - l;
}

// ================= launch (single stream, capture-safe) ======================
extern "C" void kernel_launch(void* const* d_in, const int* in_sizes, int n_in,
                              void* d_out, int out_size) {
    const int N = N_NODES, E = N_EDGES;
    const float* x = (const float*)d_in[0];
    const int* ei = (const int*)d_in[1];
    const int* src = ei;
    const int* dst = ei + E;

    const float *Wl[5], *Wr[5], *bb[5], *gg[4], *bea[4];
    int idx = 2;
    for (int i = 0; i < 5; i++) {
        Wl[i] = (const float*)d_in[idx++];
        Wr[i] = (const float*)d_in[idx++];
        bb[i] = (const float*)d_in[idx++];
    }
    for (int i = 0; i < 4; i++) {
        gg[i] = (const float*)d_in[idx++];
        bea[i] = (const float*)d_in[idx++];
    }

    const int SMG = 49152;    // 3 x 16KB stages
    cudaFuncSetAttribute(gemm_f16<0>, cudaFuncAttributeMaxDynamicSharedMemorySize, SMG);
    cudaFuncSetAttribute(gemm_f16<1>, cudaFuncAttributeMaxDynamicSharedMemorySize, SMG);

    int* di = (int*)d_out;
    int* deg = di;
    int* off = di + 50000;
    int* cur = di + 100064;
    int* col = di + 150080;
    int* bsum = di + 550080;

    zero_ints<<<(150080 + 255) / 256, 256>>>(di, 150080);
    hist_kernel<<<(E + 255) / 256, 256>>>(dst, deg, E);
    scan1<<<13, 1024>>>(deg, off, bsum);
    scan2<<<1, 32>>>(bsum);
    scan3<<<13, 1024>>>(off, bsum);
    invdeg_kernel<<<(N + 255) / 256, 256>>>(deg);
    csr_scatter<<<(E + 255) / 256, 256>>>(src, dst, off, cur, col, E);

    xconv<<<(N * 32 + 255) / 256, 256>>>(x);

    int gb = (N * 32 + 255) / 256;

    // ---- layer 1: 128 -> 128 ----
    tfold16<<<dim3(8, 4), dim3(32, 8)>>>(Wl[0], Wr[0], 128, 128, 256, 0, 0);
    biascopy<<<1, 128>>>(bb[0], 128);
    gather16<1><<<gb, 256>>>(HXIN_H, HAGG_H, off, col, 32);
    gemm_f16<0><<<dim3(1, NYB), 256, SMG>>>(HAGG_H, HXIN_H, HWT_H,
                                            N, 128, 128, 128, 0, HY_H, 1, 1);
    bn_reduce<<<1, 128>>>(128, gg[0], bea[0]);

    // ---- layer 2: 128 -> 256 ----
    tfold16<<<dim3(8, 8), dim3(32, 8)>>>(Wl[1], Wr[1], 128, 256, 256, 0, 1);
    cfold<<<1, 256>>>(Wl[1], Wr[1], bb[1], 128, 256);
    gather16<1><<<gb, 256>>>(HY_H, HAGG_H, off, col, 32);
    gemm_f16<0><<<dim3(2, NYB), 256, SMG>>>(HAGG_H, HY_H, HWT_H,
                                            N, 128, 128, 256, 1, HX_H, 1, 1);
    bn_reduce<<<1, 256>>>(256, gg[1], bea[1]);

    // ---- layer 3: 256 -> 512 ----
    tfold16<<<dim3(16, 16), dim3(32, 8)>>>(Wl[2], Wr[2], 256, 512, 512, 0, 1);
    cfold<<<2, 256>>>(Wl[2], Wr[2], bb[2], 256, 512);
    gather16<2><<<gb, 256>>>(HX_H, HAGG_H, off, col, 64);
    gemm_f16<0><<<dim3(4, NYB), 256, SMG>>>(HAGG_H, HX_H, HWT_H,
                                            N, 256, 256, 512, 1, HY_H, 1, 1);
    bn_reduce<<<2, 256>>>(512, gg[2], bea[2]);

    // ---- layer 4: 512 -> 1024 ----
    tfold16<<<dim3(32, 32), dim3(32, 8)>>>(Wl[3], Wr[3], 512, 1024, 1024, 0, 1);
    cfold<<<4, 256>>>(Wl[3], Wr[3], bb[3], 512, 1024);
    gather16<4><<<gb, 256>>>(HY_H, HAGG_H, off, col, 128);
    gemm_f16<0><<<dim3(8, NYB), 256, SMG>>>(HAGG_H, HY_H, HWT_H,
                                            N, 512, 512, 1024, 1, HX_H, 1, 1);
    bn_reduce<<<4, 256>>>(1024, gg[3], bea[3]);

    // ---- layer 5: 1024 -> 80 (z|w colsplit, padded to 128), fp32 out ----
    tfold16<<<dim3(32, 4), dim3(32, 8)>>>(Wl[4], Wr[4], 1024, 128, 1024, 1, 1);
    cfold5<<<1, 64>>>(Wl[4], Wr[4], bb[4]);
    gemm_f16<1><<<dim3(1, NYB), 256, SMG>>>(HAGG_H, HX_H, HWT_H,
                                            N, 0, 1024, 80, 0, ZW_F, 0, 0);
    gather40<<<gb, 256>>>(off, col);

    final_kernel<<<gb, 256>>>((float*)d_out, N);
}

// round 16
// speedup vs baseline: 1.1202x; 1.0146x over previous
#include <cuda_runtime.h>
#include <cuda_fp16.h>
#include <stdlib.h>
#include <math.h>
#include <stdint.h>

__attribute__((constructor)) static void _force_eager_module_load() {
    setenv("CUDA_MODULE_LOADING", "EAGER", 1);
}

#define N_NODES 50000
#define N_EDGES 400000
#define MAXD 1024
#define BN_EPS 1e-5f
#define NYB 391   // ceil(50000/128)

// ---- consolidated scratch (float units; halves view via GH) ------------------
#define HX_H    0            // N*1024 halves (big ping)
#define HY_H    51200000     // N*512 halves (pong)
#define HAGG_H  76800000     // N*512 halves (agg)
#define HXIN_H  102400000    // N*128 halves (x fp16)
#define HWT_H   108800000    // transposed fp16 weights
#define ZW_F    55500000     // N*80 fp32 (layer-5 z|w)
#define OFF2_F  59500000     // safe CSR copy: off (100,001 ints)
#define COL2_F  59700000     // safe CSR copy: col (400,000 ints)
#define IDG_F   61500000
#define ST_F    61550080     // a at +0, c at +MAXD
#define PART_F  61552128     // NYB x 2048
#define BF_F    62352896
#define CWL_F   62354944
#define SCR_TOTAL 62356224
__device__ __align__(256) float g_scr[SCR_TOTAL];
#define GH ((__half*)g_scr)
#define GI ((int*)g_scr)

// ================= CSR build (atomics only in d_out) =========================
__global__ void zero_ints(int* __restrict__ p, int n) {
    int i = blockIdx.x * blockDim.x + threadIdx.x;
    if (i < n) p[i] = 0;
}

__global__ void hist_kernel(const int* __restrict__ dst, int* __restrict__ deg, int E) {
    int i = blockIdx.x * blockDim.x + threadIdx.x;
    if (i < E) atomicAdd(&deg[dst[i]], 1);
}

__global__ void scan1(const int* __restrict__ deg, int* __restrict__ off, int* __restrict__ bsum) {
    __shared__ int sh[1024];
    int tid = threadIdx.x;
    int base = blockIdx.x * 4096 + tid * 4;
    int v0 = 0, v1 = 0, v2 = 0, v3 = 0;
    if (base + 3 < N_NODES) {
        int4 v = *(const int4*)(deg + base);
        v0 = v.x; v1 = v.y; v2 = v.z; v3 = v.w;
    } else {
        if (base + 0 < N_NODES) v0 = deg[base + 0];
        if (base + 1 < N_NODES) v1 = deg[base + 1];
        if (base + 2 < N_NODES) v2 = deg[base + 2];
        if (base + 3 < N_NODES) v3 = deg[base + 3];
    }
    int s = v0 + v1 + v2 + v3;
    sh[tid] = s;
    __syncthreads();
    for (int o = 1; o < 1024; o <<= 1) {
        int t = (tid >= o) ? sh[tid - o] : 0;
        __syncthreads();
        sh[tid] += t;
        __syncthreads();
    }
    int ex = sh[tid] - s;
    if (base + 0 < N_NODES) off[base + 0] = ex;
    if (base + 1 < N_NODES) off[base + 1] = ex + v0;
    if (base + 2 < N_NODES) off[base + 2] = ex + v0 + v1;
    if (base + 3 < N_NODES) off[base + 3] = ex + v0 + v1 + v2;
    if (tid == 1023) bsum[blockIdx.x] = sh[1023];   // raw per-block sum
}

// adds exclusive prefix of bsum (computed locally; 13 elements)
__global__ void scan3(int* __restrict__ off, const int* __restrict__ bsum) {
    int tid = threadIdx.x;
    int add = 0, total = 0;
    for (int i = 0; i < 13; i++) {
        int v = bsum[i];
        if (i < blockIdx.x) add += v;
        total += v;
    }
    int base = blockIdx.x * 4096 + tid * 4;
#pragma unroll
    for (int j = 0; j < 4; j++)
        if (base + j < N_NODES) off[base + j] += add;
    if (blockIdx.x == 0 && tid == 0) off[N_NODES] = total;
}

__global__ void invdeg_kernel(const int* __restrict__ deg) {
    int i = blockIdx.x * blockDim.x + threadIdx.x;
    if (i < N_NODES) g_scr[IDG_F + i] = (deg[i] > 0) ? (1.0f / (float)deg[i]) : 0.0f;
}

__global__ void csr_scatter(const int* __restrict__ src, const int* __restrict__ dst,
                            const int* __restrict__ off, int* __restrict__ cur,
                            int* __restrict__ col, int E) {
    int e = blockIdx.x * blockDim.x + threadIdx.x;
    if (e >= E) return;
    int d = dst[e];
    int p = atomicAdd(&cur[d], 1);
    col[off[d] + p] = src[e];
}

// copy off+col into g_scr so final_fused never reads d_out while writing it
__global__ void csr_copy(const int* __restrict__ off, const int* __restrict__ col) {
    int i = blockIdx.x * blockDim.x + threadIdx.x;
    if (i <= N_NODES) GI[OFF2_F + i] = off[i];
    int stride = gridDim.x * blockDim.x;
    for (int j = i; j < N_EDGES; j += stride) GI[COL2_F + j] = col[j];
}

// ================= x -> fp16 ==================================================
__global__ void xconv(const float* __restrict__ x) {
    int i = blockIdx.x * blockDim.x + threadIdx.x;
    if (i < N_NODES * 32) {
        float4 v = ((const float4*)x)[i];
        __half2* o = (__half2*)(GH + HXIN_H);
        o[2 * i] = __floats2half2_rn(v.x, v.y);
        o[2 * i + 1] = __floats2half2_rn(v.z, v.w);
    }
}

// ====== gather-mean fp16 (warp per node, 2-way neighbor unroll for MLP) ======
template <int NU>
__global__ void gather16(int inOffH, int outOffH,
                         const int* __restrict__ off, const int* __restrict__ col,
                         int d4) {
    const uint2* base = (const uint2*)(GH + inOffH);
    uint2* out = (uint2*)(GH + outOffH);
    int node = (blockIdx.x * blockDim.x + threadIdx.x) >> 5;
    int lane = threadIdx.x & 31;
    if (node >= N_NODES) return;
    int s = off[node], e = off[node + 1];
    float sdeg = g_scr[IDG_F + node];
    float2 acc[NU][2];
#pragma unroll
    for (int i = 0; i < NU; i++) {
        acc[i][0] = make_float2(0.f, 0.f);
        acc[i][1] = make_float2(0.f, 0.f);
    }
    int j = s;
    for (; j + 1 < e; j += 2) {
        const uint2* r0 = base + (size_t)col[j] * d4;
        const uint2* r1 = base + (size_t)col[j + 1] * d4;
        uint2 v0[NU], v1[NU];
#pragma unroll
        for (int i = 0; i < NU; i++) {
            v0[i] = r0[lane + 32 * i];
            v1[i] = r1[lane + 32 * i];
        }
#pragma unroll
        for (int i = 0; i < NU; i++) {
            uint32_t ux0 = v0[i].x, uy0 = v0[i].y, ux1 = v1[i].x, uy1 = v1[i].y;
            float2 a = __half22float2(*reinterpret_cast<__half2*>(&ux0));
            float2 b = __half22float2(*reinterpret_cast<__half2*>(&uy0));
            float2 c = __half22float2(*reinterpret_cast<__half2*>(&ux1));
            float2 d = __half22float2(*reinterpret_cast<__half2*>(&uy1));
            acc[i][0].x += a.x + c.x; acc[i][0].y += a.y + c.y;
            acc[i][1].x += b.x + d.x; acc[i][1].y += b.y + d.y;
        }
    }
    if (j < e) {
        const uint2* row = base + (size_t)col[j] * d4;
#pragma unroll
        for (int i = 0; i < NU; i++) {
            uint2 v = row[lane + 32 * i];
            uint32_t ux = v.x, uy = v.y;
            float2 f0 = __half22float2(*reinterpret_cast<__half2*>(&ux));
            float2 f1 = __half22float2(*reinterpret_cast<__half2*>(&uy));
            acc[i][0].x += f0.x; acc[i][0].y += f0.y;
            acc[i][1].x += f1.x; acc[i][1].y += f1.y;
        }
    }
    uint2* orow = out + (size_t)node * d4;
#pragma unroll
    for (int i = 0; i < NU; i++) {
        __half2 h0 = __floats2half2_rn(acc[i][0].x * sdeg, acc[i][0].y * sdeg);
        __half2 h1 = __floats2half2_rn(acc[i][1].x * sdeg, acc[i][1].y * sdeg);
        uint2 v;
        v.x = *reinterpret_cast<uint32_t*>(&h0);
        v.y = *reinterpret_cast<uint32_t*>(&h1);
        orow[lane + 32 * i] = v;
    }
}

// ================= helpers ===================================================
__device__ __forceinline__ void mma_f16(float c[4], uint32_t a0, uint32_t a1,
                                        uint32_t a2, uint32_t a3,
                                        uint32_t b0, uint32_t b1) {
    asm volatile(
        "mma.sync.aligned.m16n8k16.row.col.f32.f16.f16.f32 "
        "{%0,%1,%2,%3}, {%4,%5,%6,%7}, {%8,%9}, {%0,%1,%2,%3};"
        : "+f"(c[0]), "+f"(c[1]), "+f"(c[2]), "+f"(c[3])
        : "r"(a0), "r"(a1), "r"(a2), "r"(a3), "r"(b0), "r"(b1));
}

__device__ __forceinline__ void cp16(uint32_t dst, const void* src) {
    asm volatile("cp.async.cg.shared.global [%0], [%1], 16;\n"
                 :: "r"(dst), "l"(src) : "memory");
}

__device__ __forceinline__ void ldm4(uint32_t& r0, uint32_t& r1, uint32_t& r2,
                                     uint32_t& r3, uint32_t addr) {
    asm volatile("ldmatrix.sync.aligned.m8n8.x4.shared.b16 {%0,%1,%2,%3}, [%4];"
                 : "=r"(r0), "=r"(r1), "=r"(r2), "=r"(r3) : "r"(addr));
}

// ================= fp16 dual GEMM, BN=128, ldmatrix fragments ================
template <int OUTF32>
__global__ __launch_bounds__(256, 2) void gemm_f16(
    int aOff1, int aOff2, int wtOff,
    int M, int K1, int K2, int Nd,
    int useCwl, int outOff, int doRelu, int doBN)
{
    extern __shared__ float smem[];
    uint32_t sbase = (uint32_t)__cvta_generic_to_shared(smem);
    int tid = threadIdx.x, lane = tid & 31, wid = tid >> 5;
    int bm = blockIdx.y * 128, bn = blockIdx.x * 128;
    int wm = (wid >> 2) * 64, wn = (wid & 3) * 32;
    int lr = lane >> 2, lc = lane & 3;
    int KT = K1 + K2;
    int NCH = KT / 32;

    int l7 = lane & 7;
    int lSwz = ((l7 >> 1) & 3) << 2;
    int aRow = l7 + ((lane >> 3) & 1) * 8;
    int aG = 4 * (lane >> 4);
    int bRow = l7 + ((lane >> 4) & 1) * 8;
    int bG = 4 * ((lane >> 3) & 1);

    float acc[4][4][4];
#pragma unroll
    for (int i = 0; i < 4; i++)
#pragma unroll
        for (int j = 0; j < 4; j++)
#pragma unroll
            for (int k = 0; k < 4; k++) acc[i][j][k] = 0.0f;

    auto issue = [&](int st, int c) {
        uint32_t aReg = sbase + st * 16384;
        uint32_t bReg = aReg + 8192;
        int ck = c * 32;
        const __half* Asrc;
        int astride, acol;
        if (ck < K1) { Asrc = GH + aOff1; astride = K1; acol = ck; }
        else         { Asrc = GH + aOff2; astride = K2; acol = ck - K1; }
#pragma unroll
        for (int i = 0; i < 2; i++) {
            int idx = tid + i * 256;
            int r = idx >> 2, c16 = idx & 3;
            int ar = bm + r; if (ar >= M) ar = M - 1;
            const void* src = Asrc + (size_t)ar * astride + acol + c16 * 8;
            int w = (c16 * 4) ^ (((r >> 1) & 3) << 2);
            cp16(aReg + (uint32_t)(r * 64 + w * 4), src);
        }
#pragma unroll
        for (int i = 0; i < 2; i++) {
            int idx = tid + i * 256;
            int n = idx >> 2, c16 = idx & 3;
            const void* src = GH + wtOff + (size_t)(bn + n) * KT + ck + c16 * 8;
            int w = (c16 * 4) ^ (((n >> 1) & 3) << 2);
            cp16(bReg + (uint32_t)(n * 64 + w * 4), src);
        }
        asm volatile("cp.async.commit_group;\n" ::: "memory");
    };

    issue(0, 0);
    if (NCH > 1) issue(1, 1);
    else asm volatile("cp.async.commit_group;\n" ::: "memory");

    int s = 0;
    for (int c = 0; c < NCH; c++) {
        asm volatile("cp.async.wait_group 1;\n" ::: "memory");
        __syncthreads();
        int s2 = s + 2; if (s2 >= 3) s2 -= 3;
        if (c + 2 < NCH) issue(s2, c + 2);
        else asm volatile("cp.async.commit_group;\n" ::: "memory");

        uint32_t aBase = sbase + s * 16384;
        uint32_t bBase = aBase + 8192;
#pragma unroll
        for (int ks = 0; ks < 2; ks++) {
            uint32_t af[4][4], bf[4][2];
            int gA = (8 * ks + aG) ^ lSwz;
            int gB = (8 * ks + bG) ^ lSwz;
#pragma unroll
            for (int mt = 0; mt < 4; mt++) {
                int row = wm + mt * 16 + aRow;
                ldm4(af[mt][0], af[mt][1], af[mt][2], af[mt][3],
                     aBase + (uint32_t)((row * 16 + gA) * 4));
            }
#pragma unroll
            for (int t = 0; t < 2; t++) {
                int n = wn + t * 16 + bRow;
                ldm4(bf[2 * t][0], bf[2 * t][1], bf[2 * t + 1][0], bf[2 * t + 1][1],
                     bBase + (uint32_t)((n * 16 + gB) * 4));
            }
#pragma unroll
            for (int mt = 0; mt < 4; mt++)
#pragma unroll
                for (int nt = 0; nt < 4; nt++)
                    mma_f16(acc[mt][nt], af[mt][0], af[mt][1], af[mt][2], af[mt][3],
                            bf[nt][0], bf[nt][1]);
        }
        s = s + 1; if (s >= 3) s -= 3;
    }

    // ---- epilogue ----
    float sc[4][2], qc[4][2];
#pragma unroll
    for (int nt = 0; nt < 4; nt++) { sc[nt][0] = sc[nt][1] = qc[nt][0] = qc[nt][1] = 0.f; }

#pragma unroll
    for (int mt = 0; mt < 4; mt++) {
        int r0 = bm + wm + mt * 16 + lr;
        float gate0 = 0.f, gate1 = 0.f;
        if (useCwl) {
            if (r0 < M)     gate0 = (g_scr[IDG_F + r0] != 0.f) ? 1.f : 0.f;
            if (r0 + 8 < M) gate1 = (g_scr[IDG_F + r0 + 8] != 0.f) ? 1.f : 0.f;
        }
#pragma unroll
        for (int nt = 0; nt < 4; nt++) {
            int cc = bn + wn + nt * 8 + 2 * lc;
            if (cc < Nd) {
                float b0 = g_scr[BF_F + cc], b1 = g_scr[BF_F + cc + 1];
                float w0 = useCwl ? g_scr[CWL_F + cc] : 0.f;
                float w1 = useCwl ? g_scr[CWL_F + cc + 1] : 0.f;
                if (r0 < M) {
                    float v0 = acc[mt][nt][0] + b0 + gate0 * w0;
                    float v1 = acc[mt][nt][1] + b1 + gate0 * w1;
                    if (doRelu) { v0 = fmaxf(v0, 0.f); v1 = fmaxf(v1, 0.f); }
                    if (OUTF32) {
                        *reinterpret_cast<float2*>(g_scr + outOff + (size_t)r0 * Nd + cc) =
                            make_float2(v0, v1);
                    } else {
                        *reinterpret_cast<__half2*>(GH + outOff + (size_t)r0 * Nd + cc) =
                            __floats2half2_rn(v0, v1);
                    }
                    sc[nt][0] += v0; qc[nt][0] += v0 * v0;
                    sc[nt][1] += v1; qc[nt][1] += v1 * v1;
                }
                if (r0 + 8 < M) {
                    float v0 = acc[mt][nt][2] + b0 + gate1 * w0;
                    float v1 = acc[mt][nt][3] + b1 + gate1 * w1;
                    if (doRelu) { v0 = fmaxf(v0, 0.f); v1 = fmaxf(v1, 0.f); }
                    if (OUTF32) {
                        *reinterpret_cast<float2*>(g_scr + outOff + (size_t)(r0 + 8) * Nd + cc) =
                            make_float2(v0, v1);
                    } else {
                        *reinterpret_cast<__half2*>(GH + outOff + (size_t)(r0 + 8) * Nd + cc) =
                            __floats2half2_rn(v0, v1);
                    }
                    sc[nt][0] += v0; qc[nt][0] += v0 * v0;
                    sc[nt][1] += v1; qc[nt][1] += v1 * v1;
                }
            }
        }
    }

    if (doBN) {
        __syncthreads();
        float* redS = smem;
        float* redQ = smem + 256;
#pragma unroll
        for (int nt = 0; nt < 4; nt++) {
#pragma unroll
            for (int j = 0; j < 2; j++) {
                float v = sc[nt][j], q = qc[nt][j];
                v += __shfl_xor_sync(0xFFFFFFFFu, v, 4);
                v += __shfl_xor_sync(0xFFFFFFFFu, v, 8);
                v += __shfl_xor_sync(0xFFFFFFFFu, v, 16);
                q += __shfl_xor_sync(0xFFFFFFFFu, q, 4);
                q += __shfl_xor_sync(0xFFFFFFFFu, q, 8);
                q += __shfl_xor_sync(0xFFFFFFFFu, q, 16);
                if (lr == 0) {
                    redS[wid * 32 + nt * 8 + 2 * lc + j] = v;
                    redQ[wid * 32 + nt * 8 + 2 * lc + j] = q;
                }
            }
        }
        __syncthreads();
        if (tid < 128) {
            int wg = tid >> 5, c2 = tid & 31;
            float sv = redS[wg * 32 + c2] + redS[(wg + 4) * 32 + c2];
            float qv = redQ[wg * 32 + c2] + redQ[(wg + 4) * 32 + c2];
            int colG = bn + wg * 32 + c2;
            if (colG < Nd) {
                g_scr[PART_F + (size_t)blockIdx.y * 2048 + colG] = sv;
                g_scr[PART_F + (size_t)blockIdx.y * 2048 + 1024 + colG] = qv;
            }
        }
    }
}

// ================= BN partial reduce -> (a, c) ===============================
__global__ void bn_reduce(int d, const float* __restrict__ g, const float* __restrict__ be) {
    int colI = blockIdx.x * blockDim.x + threadIdx.x;
    if (colI >= d) return;
    float s = 0.f, q = 0.f;
    for (int p = 0; p < NYB; p++) {
        s += g_scr[PART_F + (size_t)p * 2048 + colI];
        q += g_scr[PART_F + (size_t)p * 2048 + 1024 + colI];
    }
    float invM = 1.0f / (float)N_NODES;
    float mean = s * invM;
    float var = q * invM - mean * mean;
    float a = g[colI] * rsqrtf(var + BN_EPS);
    g_scr[ST_F + colI] = a;
    g_scr[ST_F + MAXD + colI] = be[colI] - mean * a;
}

// ================= transposed fp16 weight fold ===============================
__global__ void tfold16(const float* __restrict__ Wl, const float* __restrict__ Wr,
                        int din, int dout, int KT, int mode, int useScale) {
    __shared__ float tile[32][33];
    int k0 = blockIdx.x * 32, n0 = blockIdx.y * 32;
    int tx = threadIdx.x, ty = threadIdx.y;
#pragma unroll
    for (int j = 0; j < 4; j++) {
        int k = k0 + ty + j * 8;
        float w;
        if (mode == 0) {
            w = (k < din) ? Wl[(size_t)k * dout + n0 + tx]
                          : Wr[(size_t)(k - din) * dout + n0 + tx];
        } else {
            int n = n0 + tx;
            w = (n < 40) ? Wl[(size_t)k * 40 + n]
                         : ((n < 80) ? Wr[(size_t)k * 40 + n - 40] : 0.f);
        }
        tile[ty + j * 8][tx] = w;
    }
    __syncthreads();
#pragma unroll
    for (int j = 0; j < 4; j++) {
        int n = n0 + ty + j * 8;
        int k = k0 + tx;
        float a = 1.f;
        if (useScale) {
            int kk = (mode == 0 && k >= din) ? k - din : k;
            a = g_scr[ST_F + kk];
        }
        GH[HWT_H + (size_t)n * KT + k] = __float2half(a * tile[tx][ty + j * 8]);
    }
}

__global__ void cfold(const float* __restrict__ Wl, const float* __restrict__ Wr,
                      const float* __restrict__ b, int din, int dout) {
    int n = blockIdx.x * blockDim.x + threadIdx.x;
    if (n >= dout) return;
    float sl = 0.f, sw = 0.f;
    for (int k = 0; k < din; k++) {
        float c = g_scr[ST_F + MAXD + k];
        sl += c * Wl[(size_t)k * dout + n];
        sw += c * Wr[(size_t)k * dout + n];
    }
    g_scr[CWL_F + n] = sl;
    g_scr[BF_F + n] = b[n] + sw;
}

__global__ void cfold5(const float* __restrict__ Wl, const float* __restrict__ Wr,
                       const float* __restrict__ b) {
    int n = threadIdx.x;
    if (n >= 40) return;
    float sl = 0.f, sw = 0.f;
    for (int k = 0; k < 1024; k++) {
        float c = g_scr[ST_F + MAXD + k];
        sl += c * Wl[(size_t)k * 40 + n];
        sw += c * Wr[(size_t)k * 40 + n];
    }
    g_scr[CWL_F + n] = sl;
    g_scr[BF_F + n] = 0.f;
    g_scr[BF_F + 40 + n] = b[n] + sw;
}

__global__ void biascopy(const float* __restrict__ b, int d) {
    int n = blockIdx.x * blockDim.x + threadIdx.x;
    if (n < d) { g_scr[BF_F + n] = b[n]; g_scr[CWL_F + n] = 0.f; }
}

// ======== final: fused 40-dim gather + combine + log_softmax =================
// Reads CSR from the g_scr COPY (OFF2/COL2) — never touches d_out except writes.
__global__ void final_fused(float* __restrict__ out, int M) {
    __shared__ float4 sagg[8][10];
    int w = threadIdx.x >> 5;
    int node = (blockIdx.x * blockDim.x + threadIdx.x) >> 5;
    int lane = threadIdx.x & 31;
    if (node >= M) return;
    float sdeg = g_scr[IDG_F + node];
    float gate = (sdeg != 0.f) ? 1.f : 0.f;

    if (lane < 10) {
        const float4* base = (const float4*)(g_scr + ZW_F);
        int s = GI[OFF2_F + node], e = GI[OFF2_F + node + 1];
        float4 acc = make_float4(0.f, 0.f, 0.f, 0.f);
        for (int j = s; j < e; j++) {
            float4 v = base[(size_t)GI[COL2_F + j] * 20 + lane];
            acc.x += v.x; acc.y += v.y; acc.z += v.z; acc.w += v.w;
        }
        acc.x *= sdeg; acc.y *= sdeg; acc.z *= sdeg; acc.w *= sdeg;
        sagg[w][lane] = acc;
    }
    __syncwarp();
    const float* sa = (const float*)sagg[w];

    long long zb = (long long)node * 80;
    int c1 = lane + 32;
    bool has1 = c1 < 40;
    float a0 = sa[lane] + gate * g_scr[CWL_F + lane] + g_scr[ZW_F + zb + 40 + lane];
    float a1 = has1 ? (sa[c1] + gate * g_scr[CWL_F + c1] + g_scr[ZW_F + zb + 40 + c1])
                    : -INFINITY;
    float mx = fmaxf(a0, a1);
#pragma unroll
    for (int o = 16; o; o >>= 1) mx = fmaxf(mx, __shfl_xor_sync(0xFFFFFFFFu, mx, o));
    float e = expf(a0 - mx) + (has1 ? expf(a1 - mx) : 0.f);
#pragma unroll
    for (int o = 16; o; o >>= 1) e += __shfl_xor_sync(0xFFFFFFFFu, e, o);
    float l = logf(e);
    out[(long long)node * 40 + lane] = a0 - mx - l;
    if (has1) out[(long long)node * 40 + c1] = a1 - mx - l;
}

// ================= launch (single stream, capture-safe) ======================
extern "C" void kernel_launch(void* const* d_in, const int* in_sizes, int n_in,
                              void* d_out, int out_size) {
    const int N = N_NODES, E = N_EDGES;
    const float* x = (const float*)d_in[0];
    const int* ei = (const int*)d_in[1];
    const int* src = ei;
    const int* dst = ei + E;

    const float *Wl[5], *Wr[5], *bb[5], *gg[4], *bea[4];
    int idx = 2;
    for (int i = 0; i < 5; i++) {
        Wl[i] = (const float*)d_in[idx++];
        Wr[i] = (const float*)d_in[idx++];
        bb[i] = (const float*)d_in[idx++];
    }
    for (int i = 0; i < 4; i++) {
        gg[i] = (const float*)d_in[idx++];
        bea[i] = (const float*)d_in[idx++];
    }

    const int SMG = 49152;    // 3 x 16KB stages
    cudaFuncSetAttribute(gemm_f16<0>, cudaFuncAttributeMaxDynamicSharedMemorySize, SMG);
    cudaFuncSetAttribute(gemm_f16<1>, cudaFuncAttributeMaxDynamicSharedMemorySize, SMG);

    int* di = (int*)d_out;
    int* deg = di;                  // [0, 50000)
    int* off = di + 50000;          // [50000, 100001)
    int* cur = di + 100064;         // [100064, 150064)
    int* col = di + 150080;
    int* bsum = di + 550080;

    zero_ints<<<(50000 + 255) / 256, 256>>>(deg, 50000);
    zero_ints<<<(50000 + 255) / 256, 256>>>(cur, 50000);
    hist_kernel<<<(E + 255) / 256, 256>>>(dst, deg, E);
    scan1<<<13, 1024>>>(deg, off, bsum);
    scan3<<<13, 1024>>>(off, bsum);
    invdeg_kernel<<<(N + 255) / 256, 256>>>(deg);
    csr_scatter<<<(E + 255) / 256, 256>>>(src, dst, off, cur, col, E);
    csr_copy<<<(400000 + 255) / 256, 256>>>(off, col);

    xconv<<<(N * 32 + 255) / 256, 256>>>(x);

    int gb = (N * 32 + 255) / 256;

    // ---- layer 1: 128 -> 128 ----
    tfold16<<<dim3(8, 4), dim3(32, 8)>>>(Wl[0], Wr[0], 128, 128, 256, 0, 0);
    biascopy<<<1, 128>>>(bb[0], 128);
    gather16<1><<<gb, 256>>>(HXIN_H, HAGG_H, off, col, 32);
    gemm_f16<0><<<dim3(1, NYB), 256, SMG>>>(HAGG_H, HXIN_H, HWT_H,
                                            N, 128, 128, 128, 0, HY_H, 1, 1);
    bn_reduce<<<1, 128>>>(128, gg[0], bea[0]);

    // ---- layer 2: 128 -> 256 ----
    tfold16<<<dim3(8, 8), dim3(32, 8)>>>(Wl[1], Wr[1], 128, 256, 256, 0, 1);
    cfold<<<1, 256>>>(Wl[1], Wr[1], bb[1], 128, 256);
    gather16<1><<<gb, 256>>>(HY_H, HAGG_H, off, col, 32);
    gemm_f16<0><<<dim3(2, NYB), 256, SMG>>>(HAGG_H, HY_H, HWT_H,
                                            N, 128, 128, 256, 1, HX_H, 1, 1);
    bn_reduce<<<1, 256>>>(256, gg[1], bea[1]);

    // ---- layer 3: 256 -> 512 ----
    tfold16<<<dim3(16, 16), dim3(32, 8)>>>(Wl[2], Wr[2], 256, 512, 512, 0, 1);
    cfold<<<2, 256>>>(Wl[2], Wr[2], bb[2], 256, 512);
    gather16<2><<<gb, 256>>>(HX_H, HAGG_H, off, col, 64);
    gemm_f16<0><<<dim3(4, NYB), 256, SMG>>>(HAGG_H, HX_H, HWT_H,
                                            N, 256, 256, 512, 1, HY_H, 1, 1);
    bn_reduce<<<2, 256>>>(512, gg[2], bea[2]);

    // ---- layer 4: 512 -> 1024 ----
    tfold16<<<dim3(32, 32), dim3(32, 8)>>>(Wl[3], Wr[3], 512, 1024, 1024, 0, 1);
    cfold<<<4, 256>>>(Wl[3], Wr[3], bb[3], 512, 1024);
    gather16<4><<<gb, 256>>>(HY_H, HAGG_H, off, col, 128);
    gemm_f16<0><<<dim3(8, NYB), 256, SMG>>>(HAGG_H, HY_H, HWT_H,
                                            N, 512, 512, 1024, 1, HX_H, 1, 1);
    bn_reduce<<<4, 256>>>(1024, gg[3], bea[3]);

    // ---- layer 5: 1024 -> 80 (z|w colsplit, padded to 128), fp32 out ----
    tfold16<<<dim3(32, 4), dim3(32, 8)>>>(Wl[4], Wr[4], 1024, 128, 1024, 1, 1);
    cfold5<<<1, 64>>>(Wl[4], Wr[4], bb[4]);
    gemm_f16<1><<<dim3(1, NYB), 256, SMG>>>(HAGG_H, HX_H, HWT_H,
                                            N, 0, 1024, 80, 0, ZW_F, 0, 0);

    final_fused<<<gb, 256>>>((float*)d_out, N);
}

// round 17
// speedup vs baseline: 1.1348x; 1.0130x over previous
#include <cuda_runtime.h>
#include <cuda_fp16.h>
#include <stdlib.h>
#include <math.h>
#include <stdint.h>

__attribute__((constructor)) static void _force_eager_module_load() {
    setenv("CUDA_MODULE_LOADING", "EAGER", 1);
}

#define N_NODES 50000
#define N_EDGES 400000
#define MAXD 1024
#define BN_EPS 1e-5f
#define NYB 391   // ceil(50000/128)

// ---- consolidated scratch (float units; halves view via GH) ------------------
#define HX_H    0            // N*1024 halves (big ping)
#define HY_H    51200000     // N*512 halves (pong)
#define HAGG_H  76800000     // N*512 halves (agg)
#define HXIN_H  102400000    // N*128 halves (x fp16)
#define HWT_H   108800000    // transposed fp16 weights
#define ZW_F    55500000     // N*80 fp32 (layer-5 z|w)
#define OFF2_F  59500000     // safe CSR copy: off
#define COL2_F  59700000     // safe CSR copy: col
#define IDG_F   61500000
#define ST_F    61550080     // a at +0, c at +MAXD
#define PART_F  61552128     // NYB x 2048
#define BF_F    62352896
#define CWL_F   62354944
#define SCR_TOTAL 62356224
__device__ __align__(256) float g_scr[SCR_TOTAL];
#define GH ((__half*)g_scr)
#define GI ((int*)g_scr)

// ================= CSR build (atomics only in d_out) =========================
__global__ void zero_ints(int* __restrict__ p, int n) {
    int i = blockIdx.x * blockDim.x + threadIdx.x;
    if (i < n) p[i] = 0;
}

__global__ void hist_kernel(const int* __restrict__ dst, int* __restrict__ deg, int E) {
    int i = blockIdx.x * blockDim.x + threadIdx.x;
    if (i < E) atomicAdd(&deg[dst[i]], 1);
}

__global__ void scan1(const int* __restrict__ deg, int* __restrict__ off, int* __restrict__ bsum) {
    __shared__ int sh[1024];
    int tid = threadIdx.x;
    int base = blockIdx.x * 4096 + tid * 4;
    int v0 = 0, v1 = 0, v2 = 0, v3 = 0;
    if (base + 3 < N_NODES) {
        int4 v = *(const int4*)(deg + base);
        v0 = v.x; v1 = v.y; v2 = v.z; v3 = v.w;
    } else {
        if (base + 0 < N_NODES) v0 = deg[base + 0];
        if (base + 1 < N_NODES) v1 = deg[base + 1];
        if (base + 2 < N_NODES) v2 = deg[base + 2];
        if (base + 3 < N_NODES) v3 = deg[base + 3];
    }
    int s = v0 + v1 + v2 + v3;
    sh[tid] = s;
    __syncthreads();
    for (int o = 1; o < 1024; o <<= 1) {
        int t = (tid >= o) ? sh[tid - o] : 0;
        __syncthreads();
        sh[tid] += t;
        __syncthreads();
    }
    int ex = sh[tid] - s;
    if (base + 0 < N_NODES) off[base + 0] = ex;
    if (base + 1 < N_NODES) off[base + 1] = ex + v0;
    if (base + 2 < N_NODES) off[base + 2] = ex + v0 + v1;
    if (base + 3 < N_NODES) off[base + 3] = ex + v0 + v1 + v2;
    if (tid == 1023) bsum[blockIdx.x] = sh[1023];
}

__global__ void scan3(int* __restrict__ off, const int* __restrict__ bsum) {
    int tid = threadIdx.x;
    int add = 0, total = 0;
    for (int i = 0; i < 13; i++) {
        int v = bsum[i];
        if (i < blockIdx.x) add += v;
        total += v;
    }
    int base = blockIdx.x * 4096 + tid * 4;
#pragma unroll
    for (int j = 0; j < 4; j++)
        if (base + j < N_NODES) off[base + j] += add;
    if (blockIdx.x == 0 && tid == 0) off[N_NODES] = total;
}

__global__ void invdeg_kernel(const int* __restrict__ deg) {
    int i = blockIdx.x * blockDim.x + threadIdx.x;
    if (i < N_NODES) g_scr[IDG_F + i] = (deg[i] > 0) ? (1.0f / (float)deg[i]) : 0.0f;
}

__global__ void csr_scatter(const int* __restrict__ src, const int* __restrict__ dst,
                            const int* __restrict__ off, int* __restrict__ cur,
                            int* __restrict__ col, int E) {
    int e = blockIdx.x * blockDim.x + threadIdx.x;
    if (e >= E) return;
    int d = dst[e];
    int p = atomicAdd(&cur[d], 1);
    col[off[d] + p] = src[e];
}

__global__ void csr_copy(const int* __restrict__ off, const int* __restrict__ col) {
    int i = blockIdx.x * blockDim.x + threadIdx.x;
    if (i <= N_NODES) GI[OFF2_F + i] = off[i];
    int stride = gridDim.x * blockDim.x;
    for (int j = i; j < N_EDGES; j += stride) GI[COL2_F + j] = col[j];
}

// ================= x -> fp16 ==================================================
__global__ void xconv(const float* __restrict__ x) {
    int i = blockIdx.x * blockDim.x + threadIdx.x;
    if (i < N_NODES * 32) {
        float4 v = ((const float4*)x)[i];
        __half2* o = (__half2*)(GH + HXIN_H);
        o[2 * i] = __floats2half2_rn(v.x, v.y);
        o[2 * i + 1] = __floats2half2_rn(v.z, v.w);
    }
}

// ====== gather-mean fp16 (warp per node, 2-way neighbor unroll) ==============
template <int NU>
__global__ void gather16(int inOffH, int outOffH,
                         const int* __restrict__ off, const int* __restrict__ col,
                         int d4) {
    const uint2* base = (const uint2*)(GH + inOffH);
    uint2* out = (uint2*)(GH + outOffH);
    int node = (blockIdx.x * blockDim.x + threadIdx.x) >> 5;
    int lane = threadIdx.x & 31;
    if (node >= N_NODES) return;
    int s = off[node], e = off[node + 1];
    float sdeg = g_scr[IDG_F + node];
    float2 acc[NU][2];
#pragma unroll
    for (int i = 0; i < NU; i++) {
        acc[i][0] = make_float2(0.f, 0.f);
        acc[i][1] = make_float2(0.f, 0.f);
    }
    int j = s;
    for (; j + 1 < e; j += 2) {
        const uint2* r0 = base + (size_t)col[j] * d4;
        const uint2* r1 = base + (size_t)col[j + 1] * d4;
        uint2 v0[NU], v1[NU];
#pragma unroll
        for (int i = 0; i < NU; i++) {
            v0[i] = r0[lane + 32 * i];
            v1[i] = r1[lane + 32 * i];
        }
#pragma unroll
        for (int i = 0; i < NU; i++) {
            uint32_t ux0 = v0[i].x, uy0 = v0[i].y, ux1 = v1[i].x, uy1 = v1[i].y;
            float2 a = __half22float2(*reinterpret_cast<__half2*>(&ux0));
            float2 b = __half22float2(*reinterpret_cast<__half2*>(&uy0));
            float2 c = __half22float2(*reinterpret_cast<__half2*>(&ux1));
            float2 d = __half22float2(*reinterpret_cast<__half2*>(&uy1));
            acc[i][0].x += a.x + c.x; acc[i][0].y += a.y + c.y;
            acc[i][1].x += b.x + d.x; acc[i][1].y += b.y + d.y;
        }
    }
    if (j < e) {
        const uint2* row = base + (size_t)col[j] * d4;
#pragma unroll
        for (int i = 0; i < NU; i++) {
            uint2 v = row[lane + 32 * i];
            uint32_t ux = v.x, uy = v.y;
            float2 f0 = __half22float2(*reinterpret_cast<__half2*>(&ux));
            float2 f1 = __half22float2(*reinterpret_cast<__half2*>(&uy));
            acc[i][0].x += f0.x; acc[i][0].y += f0.y;
            acc[i][1].x += f1.x; acc[i][1].y += f1.y;
        }
    }
    uint2* orow = out + (size_t)node * d4;
#pragma unroll
    for (int i = 0; i < NU; i++) {
        __half2 h0 = __floats2half2_rn(acc[i][0].x * sdeg, acc[i][0].y * sdeg);
        __half2 h1 = __floats2half2_rn(acc[i][1].x * sdeg, acc[i][1].y * sdeg);
        uint2 v;
        v.x = *reinterpret_cast<uint32_t*>(&h0);
        v.y = *reinterpret_cast<uint32_t*>(&h1);
        orow[lane + 32 * i] = v;
    }
}

// ================= helpers ===================================================
__device__ __forceinline__ void mma_f16(float c[4], uint32_t a0, uint32_t a1,
                                        uint32_t a2, uint32_t a3,
                                        uint32_t b0, uint32_t b1) {
    asm volatile(
        "mma.sync.aligned.m16n8k16.row.col.f32.f16.f16.f32 "
        "{%0,%1,%2,%3}, {%4,%5,%6,%7}, {%8,%9}, {%0,%1,%2,%3};"
        : "+f"(c[0]), "+f"(c[1]), "+f"(c[2]), "+f"(c[3])
        : "r"(a0), "r"(a1), "r"(a2), "r"(a3), "r"(b0), "r"(b1));
}

__device__ __forceinline__ void cp16(uint32_t dst, const void* src) {
    asm volatile("cp.async.cg.shared.global [%0], [%1], 16;\n"
                 :: "r"(dst), "l"(src) : "memory");
}

__device__ __forceinline__ void ldm4(uint32_t& r0, uint32_t& r1, uint32_t& r2,
                                     uint32_t& r3, uint32_t addr) {
    asm volatile("ldmatrix.sync.aligned.m8n8.x4.shared.b16 {%0,%1,%2,%3}, [%4];"
                 : "=r"(r0), "=r"(r1), "=r"(r2), "=r"(r3) : "r"(addr));
}

// ======== fp16 dual GEMM, BN=128, ldmatrix fragments, 4-stage pipeline =======
template <int OUTF32>
__global__ __launch_bounds__(256, 2) void gemm_f16(
    int aOff1, int aOff2, int wtOff,
    int M, int K1, int K2, int Nd,
    int useCwl, int outOff, int doRelu, int doBN)
{
    extern __shared__ float smem[];
    uint32_t sbase = (uint32_t)__cvta_generic_to_shared(smem);
    int tid = threadIdx.x, lane = tid & 31, wid = tid >> 5;
    int bm = blockIdx.y * 128, bn = blockIdx.x * 128;
    int wm = (wid >> 2) * 64, wn = (wid & 3) * 32;
    int lr = lane >> 2, lc = lane & 3;
    int KT = K1 + K2;
    int NCH = KT / 32;

    int l7 = lane & 7;
    int lSwz = ((l7 >> 1) & 3) << 2;
    int aRow = l7 + ((lane >> 3) & 1) * 8;
    int aG = 4 * (lane >> 4);
    int bRow = l7 + ((lane >> 4) & 1) * 8;
    int bG = 4 * ((lane >> 3) & 1);

    float acc[4][4][4];
#pragma unroll
    for (int i = 0; i < 4; i++)
#pragma unroll
        for (int j = 0; j < 4; j++)
#pragma unroll
            for (int k = 0; k < 4; k++) acc[i][j][k] = 0.0f;

    auto issue = [&](int st, int c) {
        uint32_t aReg = sbase + st * 16384;
        uint32_t bReg = aReg + 8192;
        int ck = c * 32;
        const __half* Asrc;
        int astride, acol;
        if (ck < K1) { Asrc = GH + aOff1; astride = K1; acol = ck; }
        else         { Asrc = GH + aOff2; astride = K2; acol = ck - K1; }
#pragma unroll
        for (int i = 0; i < 2; i++) {
            int idx = tid + i * 256;
            int r = idx >> 2, c16 = idx & 3;
            int ar = bm + r; if (ar >= M) ar = M - 1;
            const void* src = Asrc + (size_t)ar * astride + acol + c16 * 8;
            int w = (c16 * 4) ^ (((r >> 1) & 3) << 2);
            cp16(aReg + (uint32_t)(r * 64 + w * 4), src);
        }
#pragma unroll
        for (int i = 0; i < 2; i++) {
            int idx = tid + i * 256;
            int n = idx >> 2, c16 = idx & 3;
            const void* src = GH + wtOff + (size_t)(bn + n) * KT + ck + c16 * 8;
            int w = (c16 * 4) ^ (((n >> 1) & 3) << 2);
            cp16(bReg + (uint32_t)(n * 64 + w * 4), src);
        }
        asm volatile("cp.async.commit_group;\n" ::: "memory");
    };

    // prime 3 stages (NCH >= 8 for every layer here)
    issue(0, 0);
    issue(1, 1);
    issue(2, 2);

    for (int c = 0; c < NCH; c++) {
        asm volatile("cp.async.wait_group 2;\n" ::: "memory");
        __syncthreads();
        int s = c & 3;
        int s3 = (c + 3) & 3;
        if (c + 3 < NCH) issue(s3, c + 3);
        else asm volatile("cp.async.commit_group;\n" ::: "memory");

        uint32_t aBase = sbase + s * 16384;
        uint32_t bBase = aBase + 8192;
#pragma unroll
        for (int ks = 0; ks < 2; ks++) {
            uint32_t af[4][4], bf[4][2];
            int gA = (8 * ks + aG) ^ lSwz;
            int gB = (8 * ks + bG) ^ lSwz;
#pragma unroll
            for (int mt = 0; mt < 4; mt++) {
                int row = wm + mt * 16 + aRow;
                ldm4(af[mt][0], af[mt][1], af[mt][2], af[mt][3],
                     aBase + (uint32_t)((row * 16 + gA) * 4));
            }
#pragma unroll
            for (int t = 0; t < 2; t++) {
                int n = wn + t * 16 + bRow;
                ldm4(bf[2 * t][0], bf[2 * t][1], bf[2 * t + 1][0], bf[2 * t + 1][1],
                     bBase + (uint32_t)((n * 16 + gB) * 4));
            }
#pragma unroll
            for (int mt = 0; mt < 4; mt++)
#pragma unroll
                for (int nt = 0; nt < 4; nt++)
                    mma_f16(acc[mt][nt], af[mt][0], af[mt][1], af[mt][2], af[mt][3],
                            bf[nt][0], bf[nt][1]);
        }
    }

    // ---- epilogue ----
    float sc[4][2], qc[4][2];
#pragma unroll
    for (int nt = 0; nt < 4; nt++) { sc[nt][0] = sc[nt][1] = qc[nt][0] = qc[nt][1] = 0.f; }

#pragma unroll
    for (int mt = 0; mt < 4; mt++) {
        int r0 = bm + wm + mt * 16 + lr;
        float gate0 = 0.f, gate1 = 0.f;
        if (useCwl) {
            if (r0 < M)     gate0 = (g_scr[IDG_F + r0] != 0.f) ? 1.f : 0.f;
            if (r0 + 8 < M) gate1 = (g_scr[IDG_F + r0 + 8] != 0.f) ? 1.f : 0.f;
        }
#pragma unroll
        for (int nt = 0; nt < 4; nt++) {
            int cc = bn + wn + nt * 8 + 2 * lc;
            if (cc < Nd) {
                float b0 = g_scr[BF_F + cc], b1 = g_scr[BF_F + cc + 1];
                float w0 = useCwl ? g_scr[CWL_F + cc] : 0.f;
                float w1 = useCwl ? g_scr[CWL_F + cc + 1] : 0.f;
                if (r0 < M) {
                    float v0 = acc[mt][nt][0] + b0 + gate0 * w0;
                    float v1 = acc[mt][nt][1] + b1 + gate0 * w1;
                    if (doRelu) { v0 = fmaxf(v0, 0.f); v1 = fmaxf(v1, 0.f); }
                    if (OUTF32) {
                        *reinterpret_cast<float2*>(g_scr + outOff + (size_t)r0 * Nd + cc) =
                            make_float2(v0, v1);
                    } else {
                        *reinterpret_cast<__half2*>(GH + outOff + (size_t)r0 * Nd + cc) =
                            __floats2half2_rn(v0, v1);
                    }
                    sc[nt][0] += v0; qc[nt][0] += v0 * v0;
                    sc[nt][1] += v1; qc[nt][1] += v1 * v1;
                }
                if (r0 + 8 < M) {
                    float v0 = acc[mt][nt][2] + b0 + gate1 * w0;
                    float v1 = acc[mt][nt][3] + b1 + gate1 * w1;
                    if (doRelu) { v0 = fmaxf(v0, 0.f); v1 = fmaxf(v1, 0.f); }
                    if (OUTF32) {
                        *reinterpret_cast<float2*>(g_scr + outOff + (size_t)(r0 + 8) * Nd + cc) =
                            make_float2(v0, v1);
                    } else {
                        *reinterpret_cast<__half2*>(GH + outOff + (size_t)(r0 + 8) * Nd + cc) =
                            __floats2half2_rn(v0, v1);
                    }
                    sc[nt][0] += v0; qc[nt][0] += v0 * v0;
                    sc[nt][1] += v1; qc[nt][1] += v1 * v1;
                }
            }
        }
    }

    if (doBN) {
        __syncthreads();
        float* redS = smem;
        float* redQ = smem + 256;
#pragma unroll
        for (int nt = 0; nt < 4; nt++) {
#pragma unroll
            for (int j = 0; j < 2; j++) {
                float v = sc[nt][j], q = qc[nt][j];
                v += __shfl_xor_sync(0xFFFFFFFFu, v, 4);
                v += __shfl_xor_sync(0xFFFFFFFFu, v, 8);
                v += __shfl_xor_sync(0xFFFFFFFFu, v, 16);
                q += __shfl_xor_sync(0xFFFFFFFFu, q, 4);
                q += __shfl_xor_sync(0xFFFFFFFFu, q, 8);
                q += __shfl_xor_sync(0xFFFFFFFFu, q, 16);
                if (lr == 0) {
                    redS[wid * 32 + nt * 8 + 2 * lc + j] = v;
                    redQ[wid * 32 + nt * 8 + 2 * lc + j] = q;
                }
            }
        }
        __syncthreads();
        if (tid < 128) {
            int wg = tid >> 5, c2 = tid & 31;
            float sv = redS[wg * 32 + c2] + redS[(wg + 4) * 32 + c2];
            float qv = redQ[wg * 32 + c2] + redQ[(wg + 4) * 32 + c2];
            int colG = bn + wg * 32 + c2;
            if (colG < Nd) {
                g_scr[PART_F + (size_t)blockIdx.y * 2048 + colG] = sv;
                g_scr[PART_F + (size_t)blockIdx.y * 2048 + 1024 + colG] = qv;
            }
        }
    }
}

// ======== BN partial reduce -> (a, c): parallel 4-way k-split ================
__global__ void bn_reduce2(int d, const float* __restrict__ g, const float* __restrict__ be) {
    __shared__ float shS[4][64], shQ[4][64];
    int tx = threadIdx.x, ty = threadIdx.y;
    int colI = blockIdx.x * 64 + tx;
    bool valid = colI < d;
    float s = 0.f, q = 0.f;
    if (valid) {
        for (int p = ty; p < NYB; p += 4) {
            s += g_scr[PART_F + (size_t)p * 2048 + colI];
            q += g_scr[PART_F + (size_t)p * 2048 + 1024 + colI];
        }
    }
    shS[ty][tx] = s; shQ[ty][tx] = q;
    __syncthreads();
    if (ty == 0 && valid) {
        float ss = shS[0][tx] + shS[1][tx] + shS[2][tx] + shS[3][tx];
        float qq = shQ[0][tx] + shQ[1][tx] + shQ[2][tx] + shQ[3][tx];
        float invM = 1.0f / (float)N_NODES;
        float mean = ss * invM;
        float var = qq * invM - mean * mean;
        float a = g[colI] * rsqrtf(var + BN_EPS);
        g_scr[ST_F + colI] = a;
        g_scr[ST_F + MAXD + colI] = be[colI] - mean * a;
    }
}

// ================= transposed fp16 weight fold ===============================
__global__ void tfold16(const float* __restrict__ Wl, const float* __restrict__ Wr,
                        int din, int dout, int KT, int mode, int useScale) {
    __shared__ float tile[32][33];
    int k0 = blockIdx.x * 32, n0 = blockIdx.y * 32;
    int tx = threadIdx.x, ty = threadIdx.y;
#pragma unroll
    for (int j = 0; j < 4; j++) {
        int k = k0 + ty + j * 8;
        float w;
        if (mode == 0) {
            w = (k < din) ? Wl[(size_t)k * dout + n0 + tx]
                          : Wr[(size_t)(k - din) * dout + n0 + tx];
        } else {
            int n = n0 + tx;
            w = (n < 40) ? Wl[(size_t)k * 40 + n]
                         : ((n < 80) ? Wr[(size_t)k * 40 + n - 40] : 0.f);
        }
        tile[ty + j * 8][tx] = w;
    }
    __syncthreads();
#pragma unroll
    for (int j = 0; j < 4; j++) {
        int n = n0 + ty + j * 8;
        int k = k0 + tx;
        float a = 1.f;
        if (useScale) {
            int kk = (mode == 0 && k >= din) ? k - din : k;
            a = g_scr[ST_F + kk];
        }
        GH[HWT_H + (size_t)n * KT + k] = __float2half(a * tile[tx][ty + j * 8]);
    }
}

// ======== cwl + folded bias: parallel 4-way k-split (l5mode handles L5) ======
__global__ void cfold2(const float* __restrict__ Wl, const float* __restrict__ Wr,
                       const float* __restrict__ b, int din, int dout, int l5mode) {
    __shared__ float shL[4][64], shW[4][64];
    int tx = threadIdx.x, ty = threadIdx.y;
    int n = blockIdx.x * 64 + tx;
    bool valid = n < dout;
    int nc = valid ? n : 0;
    float sl = 0.f, sw = 0.f;
    for (int k = ty; k < din; k += 4) {
        float c = g_scr[ST_F + MAXD + k];
        sl += c * Wl[(size_t)k * dout + nc];
        sw += c * Wr[(size_t)k * dout + nc];
    }
    shL[ty][tx] = sl; shW[ty][tx] = sw;
    __syncthreads();
    if (ty == 0 && valid) {
        float l = shL[0][tx] + shL[1][tx] + shL[2][tx] + shL[3][tx];
        float w = shW[0][tx] + shW[1][tx] + shW[2][tx] + shW[3][tx];
        if (l5mode) {
            g_scr[CWL_F + n] = l;
            g_scr[BF_F + n] = 0.f;
            g_scr[BF_F + 40 + n] = b[n] + w;
        } else {
            g_scr[CWL_F + n] = l;
            g_scr[BF_F + n] = b[n] + w;
        }
    }
}

__global__ void biascopy(const float* __restrict__ b, int d) {
    int n = blockIdx.x * blockDim.x + threadIdx.x;
    if (n < d) { g_scr[BF_F + n] = b[n]; g_scr[CWL_F + n] = 0.f; }
}

// ======== final: fused 40-dim gather + combine + log_softmax =================
__global__ void final_fused(float* __restrict__ out, int M) {
    __shared__ float4 sagg[8][10];
    int w = threadIdx.x >> 5;
    int node = (blockIdx.x * blockDim.x + threadIdx.x) >> 5;
    int lane = threadIdx.x & 31;
    if (node >= M) return;
    float sdeg = g_scr[IDG_F + node];
    float gate = (sdeg != 0.f) ? 1.f : 0.f;

    if (lane < 10) {
        const float4* base = (const float4*)(g_scr + ZW_F);
        int s = GI[OFF2_F + node], e = GI[OFF2_F + node + 1];
        float4 acc = make_float4(0.f, 0.f, 0.f, 0.f);
        for (int j = s; j < e; j++) {
            float4 v = base[(size_t)GI[COL2_F + j] * 20 + lane];
            acc.x += v.x; acc.y += v.y; acc.z += v.z; acc.w += v.w;
        }
        acc.x *= sdeg; acc.y *= sdeg; acc.z *= sdeg; acc.w *= sdeg;
        sagg[w][lane] = acc;
    }
    __syncwarp();
    const float* sa = (const float*)sagg[w];

    long long zb = (long long)node * 80;
    int c1 = lane + 32;
    bool has1 = c1 < 40;
    float a0 = sa[lane] + gate * g_scr[CWL_F + lane] + g_scr[ZW_F + zb + 40 + lane];
    float a1 = has1 ? (sa[c1] + gate * g_scr[CWL_F + c1] + g_scr[ZW_F + zb + 40 + c1])
                    : -INFINITY;
    float mx = fmaxf(a0, a1);
#pragma unroll
    for (int o = 16; o; o >>= 1) mx = fmaxf(mx, __shfl_xor_sync(0xFFFFFFFFu, mx, o));
    float e = expf(a0 - mx) + (has1 ? expf(a1 - mx) : 0.f);
#pragma unroll
    for (int o = 16; o; o >>= 1) e += __shfl_xor_sync(0xFFFFFFFFu, e, o);
    float l = logf(e);
    out[(long long)node * 40 + lane] = a0 - mx - l;
    if (has1) out[(long long)node * 40 + c1] = a1 - mx - l;
}

// ================= launch (single stream, capture-safe) ======================
extern "C" void kernel_launch(void* const* d_in, const int* in_sizes, int n_in,
                              void* d_out, int out_size) {
    const int N = N_NODES, E = N_EDGES;
    const float* x = (const float*)d_in[0];
    const int* ei = (const int*)d_in[1];
    const int* src = ei;
    const int* dst = ei + E;

    const float *Wl[5], *Wr[5], *bb[5], *gg[4], *bea[4];
    int idx = 2;
    for (int i = 0; i < 5; i++) {
        Wl[i] = (const float*)d_in[idx++];
        Wr[i] = (const float*)d_in[idx++];
        bb[i] = (const float*)d_in[idx++];
    }
    for (int i = 0; i < 4; i++) {
        gg[i] = (const float*)d_in[idx++];
        bea[i] = (const float*)d_in[idx++];
    }

    const int SMG = 65536;    // 4 x 16KB stages (occupancy 2 => 128KB/SM)
    cudaFuncSetAttribute(gemm_f16<0>, cudaFuncAttributeMaxDynamicSharedMemorySize, SMG);
    cudaFuncSetAttribute(gemm_f16<1>, cudaFuncAttributeMaxDynamicSharedMemorySize, SMG);

    int* di = (int*)d_out;
    int* deg = di;
    int* off = di + 50000;
    int* cur = di + 100064;
    int* col = di + 150080;
    int* bsum = di + 550080;

    zero_ints<<<(50000 + 255) / 256, 256>>>(deg, 50000);
    zero_ints<<<(50000 + 255) / 256, 256>>>(cur, 50000);
    hist_kernel<<<(E + 255) / 256, 256>>>(dst, deg, E);
    scan1<<<13, 1024>>>(deg, off, bsum);
    scan3<<<13, 1024>>>(off, bsum);
    invdeg_kernel<<<(N + 255) / 256, 256>>>(deg);
    csr_scatter<<<(E + 255) / 256, 256>>>(src, dst, off, cur, col, E);
    csr_copy<<<(400000 + 255) / 256, 256>>>(off, col);

    xconv<<<(N * 32 + 255) / 256, 256>>>(x);

    int gb = (N * 32 + 255) / 256;
    dim3 b64(64, 4);

    // ---- layer 1: 128 -> 128 ----
    tfold16<<<dim3(8, 4), dim3(32, 8)>>>(Wl[0], Wr[0], 128, 128, 256, 0, 0);
    biascopy<<<1, 128>>>(bb[0], 128);
    gather16<1><<<gb, 256>>>(HXIN_H, HAGG_H, off, col, 32);
    gemm_f16<0><<<dim3(1, NYB), 256, SMG>>>(HAGG_H, HXIN_H, HWT_H,
                                            N, 128, 128, 128, 0, HY_H, 1, 1);
    bn_reduce2<<<2, b64>>>(128, gg[0], bea[0]);

    // ---- layer 2: 128 -> 256 ----
    tfold16<<<dim3(8, 8), dim3(32, 8)>>>(Wl[1], Wr[1], 128, 256, 256, 0, 1);
    cfold2<<<4, b64>>>(Wl[1], Wr[1], bb[1], 128, 256, 0);
    gather16<1><<<gb, 256>>>(HY_H, HAGG_H, off, col, 32);
    gemm_f16<0><<<dim3(2, NYB), 256, SMG>>>(HAGG_H, HY_H, HWT_H,
                                            N, 128, 128, 256, 1, HX_H, 1, 1);
    bn_reduce2<<<4, b64>>>(256, gg[1], bea[1]);

    // ---- layer 3: 256 -> 512 ----
    tfold16<<<dim3(16, 16), dim3(32, 8)>>>(Wl[2], Wr[2], 256, 512, 512, 0, 1);
    cfold2<<<8, b64>>>(Wl[2], Wr[2], bb[2], 256, 512, 0);
    gather16<2><<<gb, 256>>>(HX_H, HAGG_H, off, col, 64);
    gemm_f16<0><<<dim3(4, NYB), 256, SMG>>>(HAGG_H, HX_H, HWT_H,
                                            N, 256, 256, 512, 1, HY_H, 1, 1);
    bn_reduce2<<<8, b64>>>(512, gg[2], bea[2]);

    // ---- layer 4: 512 -> 1024 ----
    tfold16<<<dim3(32, 32), dim3(32, 8)>>>(Wl[3], Wr[3], 512, 1024, 1024, 0, 1);
    cfold2<<<16, b64>>>(Wl[3], Wr[3], bb[3], 512, 1024, 0);
    gather16<4><<<gb, 256>>>(HY_H, HAGG_H, off, col, 128);
    gemm_f16<0><<<dim3(8, NYB), 256, SMG>>>(HAGG_H, HY_H, HWT_H,
                                            N, 512, 512, 1024, 1, HX_H, 1, 1);
    bn_reduce2<<<16, b64>>>(1024, gg[3], bea[3]);

    // ---- layer 5: 1024 -> 80 (z|w colsplit, padded to 128), fp32 out ----
    tfold16<<<dim3(32, 4), dim3(32, 8)>>>(Wl[4], Wr[4], 1024, 128, 1024, 1, 1);
    cfold2<<<1, b64>>>(Wl[4], Wr[4], bb[4], 1024, 40, 1);
    gemm_f16<1><<<dim3(1, NYB), 256, SMG>>>(HAGG_H, HX_H, HWT_H,
                                            N, 0, 1024, 80, 0, ZW_F, 0, 0);

    final_fused<<<gb, 256>>>((float*)d_out, N);
}